// round 1
// baseline (speedup 1.0000x reference)
#include <cuda_runtime.h>
#include <cuda_bf16.h>
#include <math.h>

// ---------------- problem constants ----------------
#define NN 100000          // nodes
#define NE 1600000         // edges
#define NG 512             // graphs
#define F1 128             // IN_F == H1
#define F2 256             // H2
#define NGRP 16
#define NFAM 10

// ---------------- device scratch (no allocations allowed) ----------------
__device__ float g_xw1 [ (size_t)NN * F1 ];
__device__ float g_agg1[ (size_t)NN * F1 ];
__device__ float g_xw2 [ (size_t)NN * F2 ];
__device__ float g_agg2[ (size_t)NN * F2 ];
__device__ float g_deg [ NN ];
__device__ float g_dinv[ NN ];
__device__ float g_sums[ NG * F2 ];
__device__ float g_cnts[ NG ];
__device__ int   g_eidx[ 2 * NE ];     // [src(NE), dst(NE)] as int32
__device__ int   g_batch[ NN ];
__device__ int   g_is64;

// ---------------- dtype detection + index normalization ----------------
// If edge_index is int64 (little-endian, values in [0,1e5)), every odd 32-bit
// word is 0. For int32 data the odd words are random src values; P(64 of them
// all zero) ~ (1e-5)^64 ~ 0.
__global__ void k_detect(const unsigned int* __restrict__ e) {
    int is64 = 1;
    for (int i = 0; i < 64; i++)
        if (e[2 * i + 1] != 0u) { is64 = 0; break; }
    g_is64 = is64;
}

__global__ void k_convert(const int* __restrict__ in, int* __restrict__ out, int n) {
    int i = blockIdx.x * blockDim.x + threadIdx.x;
    if (i >= n) return;
    out[i] = g_is64 ? in[2 * i] : in[i];
}

// ---------------- degree / init ----------------
__global__ void k_init() {
    int i = blockIdx.x * blockDim.x + threadIdx.x;
    if (i < NN) g_deg[i] = 1.0f;                 // +1 self loop
    if (i < NG * F2) g_sums[i] = 0.0f;
    if (i < NG) g_cnts[i] = 0.0f;
}

__global__ void k_deg_count() {
    int e = blockIdx.x * blockDim.x + threadIdx.x;
    if (e >= NE) return;
    atomicAdd(&g_deg[g_eidx[NE + e]], 1.0f);     // dst
}

__global__ void k_dinv() {
    int i = blockIdx.x * blockDim.x + threadIdx.x;
    if (i < NN) g_dinv[i] = rsqrtf(g_deg[i]);
}

// ---------------- fp32 tiled GEMM: C[M,N] = A[M,128] * B[128,N] ----------------
// BM=64, BN=64, per-thread 4x4. A staged [m][k] with row pad 65; thread tx owns
// rows {tx, tx+16, tx+32, tx+48} -> conflict-free scalar LDS (bank = tx+16i+k).
// Epilogue writes xw and agg = xw * dinv[row]^2  (self-loop init).
// RELU_BIAS: A element = max(Araw + bias[k], 0) (used for layer-2 input).
template<int N, bool RELU_BIAS>
__launch_bounds__(256)
__global__ void k_gemm(const float* __restrict__ A, const float* __restrict__ B,
                       const float* __restrict__ bias,
                       const float* __restrict__ dinv,
                       float* __restrict__ Cxw, float* __restrict__ Cagg, int M)
{
    __shared__ float As[64][65];
    __shared__ float Bs[64][64];

    const int tid  = threadIdx.x;
    const int tx   = tid & 15;
    const int ty   = tid >> 4;
    const int row0 = blockIdx.x * 64;
    const int col0 = blockIdx.y * 64;

    float acc[4][4];
#pragma unroll
    for (int i = 0; i < 4; i++)
#pragma unroll
        for (int j = 0; j < 4; j++) acc[i][j] = 0.0f;

    for (int kh = 0; kh < 2; kh++) {
        // ---- stage A tile [64 rows][64 k] ----
#pragma unroll
        for (int it = 0; it < 4; it++) {
            int i  = tid + it * 256;          // 0..1023 float4 slots
            int m  = i >> 4;
            int k4 = i & 15;
            int row = row0 + m;
            float4 v = make_float4(0.f, 0.f, 0.f, 0.f);
            if (row < M) {
                v = *(const float4*)(A + (size_t)row * 128 + kh * 64 + k4 * 4);
                if (RELU_BIAS) {
                    float4 bb = *(const float4*)(bias + kh * 64 + k4 * 4);
                    v.x = fmaxf(v.x + bb.x, 0.f);
                    v.y = fmaxf(v.y + bb.y, 0.f);
                    v.z = fmaxf(v.z + bb.z, 0.f);
                    v.w = fmaxf(v.w + bb.w, 0.f);
                }
            }
            As[m][k4 * 4 + 0] = v.x;
            As[m][k4 * 4 + 1] = v.y;
            As[m][k4 * 4 + 2] = v.z;
            As[m][k4 * 4 + 3] = v.w;
        }
        // ---- stage B tile [64 k][64 n] ----
#pragma unroll
        for (int it = 0; it < 4; it++) {
            int i  = tid + it * 256;
            int k  = i >> 4;
            int n4 = i & 15;
            *(float4*)(&Bs[k][n4 * 4]) =
                *(const float4*)(B + (size_t)(kh * 64 + k) * N + col0 + n4 * 4);
        }
        __syncthreads();

#pragma unroll 8
        for (int k = 0; k < 64; k++) {
            float a0 = As[tx     ][k];
            float a1 = As[tx + 16][k];
            float a2 = As[tx + 32][k];
            float a3 = As[tx + 48][k];
            float4 b = *(const float4*)(&Bs[k][ty * 4]);
            acc[0][0] += a0 * b.x; acc[0][1] += a0 * b.y; acc[0][2] += a0 * b.z; acc[0][3] += a0 * b.w;
            acc[1][0] += a1 * b.x; acc[1][1] += a1 * b.y; acc[1][2] += a1 * b.z; acc[1][3] += a1 * b.w;
            acc[2][0] += a2 * b.x; acc[2][1] += a2 * b.y; acc[2][2] += a2 * b.z; acc[2][3] += a2 * b.w;
            acc[3][0] += a3 * b.x; acc[3][1] += a3 * b.y; acc[3][2] += a3 * b.z; acc[3][3] += a3 * b.w;
        }
        __syncthreads();
    }

#pragma unroll
    for (int i = 0; i < 4; i++) {
        int row = row0 + tx + 16 * i;
        if (row < M) {
            float dv = dinv[row];
            float d2 = dv * dv;
            float4 v  = make_float4(acc[i][0], acc[i][1], acc[i][2], acc[i][3]);
            float4 va = make_float4(v.x * d2, v.y * d2, v.z * d2, v.w * d2);
            size_t off = (size_t)row * N + col0 + ty * 4;
            *(float4*)(Cxw  + off) = v;
            *(float4*)(Cagg + off) = va;
        }
    }
}

// ---------------- edge scatter: agg[dst] += xw[src] * dinv[src]*dinv[dst] ----------------
template<int F>
__global__ void k_scatter(const float* __restrict__ xw, float* __restrict__ agg)
{
    const int C = F / 4;                         // float4 chunks per edge
    int tid = blockIdx.x * blockDim.x + threadIdx.x;
    int e = tid / C;
    if (e >= NE) return;
    int c = tid - e * C;
    int s = g_eidx[e];
    int d = g_eidx[NE + e];
    float coef = g_dinv[s] * g_dinv[d];
    float4 v = *(const float4*)(xw + (size_t)s * F + c * 4);
    float* o = agg + (size_t)d * F + c * 4;
    atomicAdd(o + 0, v.x * coef);
    atomicAdd(o + 1, v.y * coef);
    atomicAdd(o + 2, v.z * coef);
    atomicAdd(o + 3, v.w * coef);
}

// ---------------- pooling (batch is sorted -> register accumulation) ----------------
__global__ void k_pool()
{
    int f  = threadIdx.x;                        // 256 = F2
    int n0 = blockIdx.x * 64;
    int n1 = min(n0 + 64, NN);
    if (n0 >= NN) return;
    int curg = g_batch[n0];
    float acc = 0.0f;
    for (int n = n0; n < n1; n++) {
        int gg = g_batch[n];
        if (gg != curg) {
            atomicAdd(&g_sums[curg * F2 + f], acc);
            acc = 0.0f; curg = gg;
        }
        acc += g_agg2[(size_t)n * F2 + f];
    }
    atomicAdd(&g_sums[curg * F2 + f], acc);
}

__global__ void k_cnts()
{
    int i = blockIdx.x * blockDim.x + threadIdx.x;
    if (i < NN) atomicAdd(&g_cnts[g_batch[i]], 1.0f);
}

// ---------------- heads ----------------
// out[0 : 512*16)          = group_logits  [G, 16]
// out[8192 : 8192+16*512*10) = family_logits [16, G, 10]
__global__ void k_head(const float* __restrict__ b2,
                       const float* __restrict__ Wg, const float* __restrict__ bg,
                       const float* __restrict__ Wf, const float* __restrict__ bf,
                       float* __restrict__ out)
{
    __shared__ float p[F2];
    int b = blockIdx.x, t = threadIdx.x;
    float cnt = g_cnts[b];
    float inv = 1.0f / fmaxf(cnt, 1.0f);
    p[t] = (cnt > 0.f) ? (g_sums[b * F2 + t] * inv + b2[t]) : 0.0f;
    __syncthreads();
    if (t < NGRP) {
        float a = bg[t];
        for (int d = 0; d < F2; d++) a += p[d] * Wg[d * NGRP + t];
        out[b * NGRP + t] = a;
    } else if (t >= 64 && t < 64 + NGRP * NFAM) {
        int u = t - 64;
        int grp = u / NFAM, f = u - grp * NFAM;
        float a = bf[grp * NFAM + f];
        for (int d = 0; d < F2; d++) a += p[d] * Wf[(size_t)grp * F2 * NFAM + d * NFAM + f];
        out[NG * NGRP + (size_t)grp * NG * NFAM + b * NFAM + f] = a;
    }
}

// ---------------- launch ----------------
extern "C" void kernel_launch(void* const* d_in, const int* in_sizes, int n_in,
                              void* d_out, int out_size)
{
    const float* x    = (const float*)d_in[0];
    const void*  eidx = d_in[1];
    const void*  batc = d_in[2];
    const float* W1   = (const float*)d_in[3];
    const float* b1   = (const float*)d_in[4];
    const float* W2   = (const float*)d_in[5];
    const float* b2   = (const float*)d_in[6];
    const float* Wg   = (const float*)d_in[7];
    const float* bg   = (const float*)d_in[8];
    const float* Wf   = (const float*)d_in[9];
    const float* bf   = (const float*)d_in[10];
    float* out = (float*)d_out;

    // scratch symbol addresses (lookup only, no allocation, capture-safe)
    float *xw1, *agg1, *xw2, *agg2, *dinv;
    int *eidx32, *batch32;
    cudaGetSymbolAddress((void**)&xw1,  g_xw1);
    cudaGetSymbolAddress((void**)&agg1, g_agg1);
    cudaGetSymbolAddress((void**)&xw2,  g_xw2);
    cudaGetSymbolAddress((void**)&agg2, g_agg2);
    cudaGetSymbolAddress((void**)&dinv, g_dinv);
    cudaGetSymbolAddress((void**)&eidx32,  g_eidx);
    cudaGetSymbolAddress((void**)&batch32, g_batch);

    // 1) normalize index dtypes
    k_detect<<<1, 1>>>((const unsigned int*)eidx);
    k_convert<<<(2 * NE + 255) / 256, 256>>>((const int*)eidx, eidx32, 2 * NE);
    k_convert<<<(NN + 255) / 256, 256>>>((const int*)batc, batch32, NN);

    // 2) degree + dinv
    k_init<<<(NG * F2 + 255) / 256, 256>>>();
    k_deg_count<<<(NE + 255) / 256, 256>>>();
    k_dinv<<<(NN + 255) / 256, 256>>>();

    // 3) layer 1: xw1 = x@W1 ; agg1 = xw1*dinv^2 ; scatter
    {
        dim3 grid((NN + 63) / 64, F1 / 64);
        k_gemm<F1, false><<<grid, 256>>>(x, W1, nullptr, dinv, xw1, agg1, NN);
    }
    k_scatter<F1><<<(NE * (F1 / 4) + 255) / 256, 256>>>(xw1, agg1);

    // 4) layer 2: input = relu(agg1+b1) fused into A-load
    {
        dim3 grid((NN + 63) / 64, F2 / 64);
        k_gemm<F2, true><<<grid, 256>>>(agg1, W2, b1, dinv, xw2, agg2, NN);
    }
    k_scatter<F2><<<(NE * (F2 / 4) + 255) / 256, 256>>>(xw2, agg2);

    // 5) pool + heads
    k_pool<<<(NN + 63) / 64, 256>>>();
    k_cnts<<<(NN + 255) / 256, 256>>>();
    k_head<<<NG, 256>>>(b2, Wg, bg, Wf, bf, out);
}

// round 3
// speedup vs baseline: 2.7401x; 2.7401x over previous
#include <cuda_runtime.h>
#include <cuda_bf16.h>
#include <math.h>

// ---------------- problem constants ----------------
#define NN 100000          // nodes
#define NE 1600000         // edges
#define NG 512             // graphs
#define F1 128             // IN_F == H1
#define F2 256             // H2
#define NGRP 16
#define NFAM 10

#define SB 512
#define NBLK ((NN + SB - 1) / SB)   // 196 scan blocks

// ---------------- device scratch (no allocations allowed) ----------------
__device__ float g_xw1 [ (size_t)NN * F1 ];
__device__ float g_agg1[ (size_t)NN * F1 ];
__device__ float g_xw2 [ (size_t)NN * F2 ];
__device__ float g_agg2[ (size_t)NN * F2 ];
__device__ float g_dinv[ NN ];
__device__ float g_sums[ NG * F2 ];
__device__ float g_cnts[ NG ];
__device__ int   g_eidx[ 2 * NE ];     // [src(NE), dst(NE)] as int32
__device__ int   g_batch[ NN ];
__device__ int   g_is64;
__device__ int   g_degi  [ NN ];       // in-degree (no self loop)
__device__ int   g_off   [ NN ];       // CSR exclusive offsets
__device__ int   g_cursor[ NN ];
__device__ int   g_bsum  [ 256 ];
__device__ int   g_csr_src [ NE ];
__device__ float g_csr_coef[ NE ];

// ---------------- dtype detection + index normalization ----------------
__global__ void k_detect(const unsigned int* __restrict__ e) {
    int is64 = 1;
    for (int i = 0; i < 64; i++)
        if (e[2 * i + 1] != 0u) { is64 = 0; break; }
    g_is64 = is64;
}

__global__ void k_convert(const int* __restrict__ in, int* __restrict__ out, int n) {
    int i = blockIdx.x * blockDim.x + threadIdx.x;
    if (i >= n) return;
    out[i] = g_is64 ? in[2 * i] : in[i];
}

// ---------------- init / degree ----------------
__global__ void k_init() {
    int i = blockIdx.x * blockDim.x + threadIdx.x;
    if (i < NN) g_degi[i] = 0;
    if (i < NG * F2) g_sums[i] = 0.0f;
    if (i < NG) g_cnts[i] = 0.0f;
}

__global__ void k_deg_count() {
    int e = blockIdx.x * blockDim.x + threadIdx.x;
    if (e >= NE) return;
    atomicAdd(&g_degi[g_eidx[NE + e]], 1);       // dst
}

__global__ void k_dinv() {
    int i = blockIdx.x * blockDim.x + threadIdx.x;
    if (i < NN) g_dinv[i] = rsqrtf((float)(g_degi[i] + 1));
}

// ---------------- exclusive scan over g_degi -> g_off (3 kernels) ----------------
__global__ void k_scan_local() {
    __shared__ int sh[SB];
    int i = blockIdx.x * SB + threadIdx.x;
    int v = (i < NN) ? g_degi[i] : 0;
    sh[threadIdx.x] = v;
    __syncthreads();
    for (int off = 1; off < SB; off <<= 1) {
        int t = (threadIdx.x >= off) ? sh[threadIdx.x - off] : 0;
        __syncthreads();
        sh[threadIdx.x] += t;
        __syncthreads();
    }
    if (i < NN) g_off[i] = sh[threadIdx.x] - v;   // exclusive
    if (threadIdx.x == SB - 1) g_bsum[blockIdx.x] = sh[SB - 1];
}

__global__ void k_scan_bsum() {
    __shared__ int sh[256];
    int t = threadIdx.x;
    int v = (t < NBLK) ? g_bsum[t] : 0;
    sh[t] = v;
    __syncthreads();
    for (int off = 1; off < 256; off <<= 1) {
        int u = (t >= off) ? sh[t - off] : 0;
        __syncthreads();
        sh[t] += u;
        __syncthreads();
    }
    if (t < NBLK) g_bsum[t] = sh[t] - v;          // exclusive
}

__global__ void k_scan_add() {
    int i = blockIdx.x * SB + threadIdx.x;
    if (i < NN) {
        int o = g_off[i] + g_bsum[blockIdx.x];
        g_off[i] = o;
        g_cursor[i] = o;
    }
}

// ---------------- CSR fill: per-dst segments of (src, coef) ----------------
__global__ void k_fill() {
    int e = blockIdx.x * blockDim.x + threadIdx.x;
    if (e >= NE) return;
    int s = g_eidx[e];
    int d = g_eidx[NE + e];
    int slot = atomicAdd(&g_cursor[d], 1);
    g_csr_src[slot] = s;
    g_csr_coef[slot] = g_dinv[s] * g_dinv[d];
}

// ---------------- fp32 tiled GEMM: C[M,N] = A[M,128] * B[128,N] ----------------
template<int N, bool RELU_BIAS>
__launch_bounds__(256)
__global__ void k_gemm(const float* __restrict__ A, const float* __restrict__ B,
                       const float* __restrict__ bias,
                       const float* __restrict__ dinv,
                       float* __restrict__ Cxw, float* __restrict__ Cagg, int M)
{
    __shared__ float As[64][65];
    __shared__ float Bs[64][64];

    const int tid  = threadIdx.x;
    const int tx   = tid & 15;
    const int ty   = tid >> 4;
    const int row0 = blockIdx.x * 64;
    const int col0 = blockIdx.y * 64;

    float acc[4][4];
#pragma unroll
    for (int i = 0; i < 4; i++)
#pragma unroll
        for (int j = 0; j < 4; j++) acc[i][j] = 0.0f;

    for (int kh = 0; kh < 2; kh++) {
#pragma unroll
        for (int it = 0; it < 4; it++) {
            int i  = tid + it * 256;
            int m  = i >> 4;
            int k4 = i & 15;
            int row = row0 + m;
            float4 v = make_float4(0.f, 0.f, 0.f, 0.f);
            if (row < M) {
                v = *(const float4*)(A + (size_t)row * 128 + kh * 64 + k4 * 4);
                if (RELU_BIAS) {
                    float4 bb = *(const float4*)(bias + kh * 64 + k4 * 4);
                    v.x = fmaxf(v.x + bb.x, 0.f);
                    v.y = fmaxf(v.y + bb.y, 0.f);
                    v.z = fmaxf(v.z + bb.z, 0.f);
                    v.w = fmaxf(v.w + bb.w, 0.f);
                }
            }
            As[m][k4 * 4 + 0] = v.x;
            As[m][k4 * 4 + 1] = v.y;
            As[m][k4 * 4 + 2] = v.z;
            As[m][k4 * 4 + 3] = v.w;
        }
#pragma unroll
        for (int it = 0; it < 4; it++) {
            int i  = tid + it * 256;
            int k  = i >> 4;
            int n4 = i & 15;
            *(float4*)(&Bs[k][n4 * 4]) =
                *(const float4*)(B + (size_t)(kh * 64 + k) * N + col0 + n4 * 4);
        }
        __syncthreads();

#pragma unroll 8
        for (int k = 0; k < 64; k++) {
            float a0 = As[tx     ][k];
            float a1 = As[tx + 16][k];
            float a2 = As[tx + 32][k];
            float a3 = As[tx + 48][k];
            float4 b = *(const float4*)(&Bs[k][ty * 4]);
            acc[0][0] += a0 * b.x; acc[0][1] += a0 * b.y; acc[0][2] += a0 * b.z; acc[0][3] += a0 * b.w;
            acc[1][0] += a1 * b.x; acc[1][1] += a1 * b.y; acc[1][2] += a1 * b.z; acc[1][3] += a1 * b.w;
            acc[2][0] += a2 * b.x; acc[2][1] += a2 * b.y; acc[2][2] += a2 * b.z; acc[2][3] += a2 * b.w;
            acc[3][0] += a3 * b.x; acc[3][1] += a3 * b.y; acc[3][2] += a3 * b.z; acc[3][3] += a3 * b.w;
        }
        __syncthreads();
    }

#pragma unroll
    for (int i = 0; i < 4; i++) {
        int row = row0 + tx + 16 * i;
        if (row < M) {
            float dv = dinv[row];
            float d2 = dv * dv;
            float4 v  = make_float4(acc[i][0], acc[i][1], acc[i][2], acc[i][3]);
            float4 va = make_float4(v.x * d2, v.y * d2, v.z * d2, v.w * d2);
            size_t off = (size_t)row * N + col0 + ty * 4;
            *(float4*)(Cxw  + off) = v;
            *(float4*)(Cagg + off) = va;
        }
    }
}

// ---------------- CSR gather: agg[d] += sum_{e in in(d)} coef_e * xw[src_e] ----
// One warp per dst node; lane owns F/32 features (float4 chunks). No atomics.
template<int F>
__launch_bounds__(256)
__global__ void k_gather(const float* __restrict__ xw, float* __restrict__ agg)
{
    int warp = (blockIdx.x * 256 + threadIdx.x) >> 5;
    if (warp >= NN) return;
    int lane = threadIdx.x & 31;
    int beg = g_off[warp];
    int end = beg + g_degi[warp];

    const int R = F / 128;             // float4 chunks per lane
    float4 acc[R];
#pragma unroll
    for (int r = 0; r < R; r++) acc[r] = make_float4(0.f, 0.f, 0.f, 0.f);

    int j = beg;
    for (; j + 1 < end; j += 2) {
        int   s0 = g_csr_src[j],      s1 = g_csr_src[j + 1];
        float c0 = g_csr_coef[j],     c1 = g_csr_coef[j + 1];
#pragma unroll
        for (int r = 0; r < R; r++) {
            float4 v0 = *(const float4*)(xw + (size_t)s0 * F + r * 128 + lane * 4);
            float4 v1 = *(const float4*)(xw + (size_t)s1 * F + r * 128 + lane * 4);
            acc[r].x += c0 * v0.x + c1 * v1.x;
            acc[r].y += c0 * v0.y + c1 * v1.y;
            acc[r].z += c0 * v0.z + c1 * v1.z;
            acc[r].w += c0 * v0.w + c1 * v1.w;
        }
    }
    if (j < end) {
        int   s0 = g_csr_src[j];
        float c0 = g_csr_coef[j];
#pragma unroll
        for (int r = 0; r < R; r++) {
            float4 v0 = *(const float4*)(xw + (size_t)s0 * F + r * 128 + lane * 4);
            acc[r].x += c0 * v0.x;
            acc[r].y += c0 * v0.y;
            acc[r].z += c0 * v0.z;
            acc[r].w += c0 * v0.w;
        }
    }

#pragma unroll
    for (int r = 0; r < R; r++) {
        float* o = agg + (size_t)warp * F + r * 128 + lane * 4;
        float4 cur = *(const float4*)o;
        cur.x += acc[r].x;
        cur.y += acc[r].y;
        cur.z += acc[r].z;
        cur.w += acc[r].w;
        *(float4*)o = cur;
    }
}

// ---------------- pooling (batch sorted -> register accumulation) ----------------
__global__ void k_pool()
{
    int f  = threadIdx.x;                        // 256 = F2
    int n0 = blockIdx.x * 64;
    int n1 = min(n0 + 64, NN);
    if (n0 >= NN) return;
    int curg = g_batch[n0];
    float acc = 0.0f;
    for (int n = n0; n < n1; n++) {
        int gg = g_batch[n];
        if (gg != curg) {
            atomicAdd(&g_sums[curg * F2 + f], acc);
            acc = 0.0f; curg = gg;
        }
        acc += g_agg2[(size_t)n * F2 + f];
    }
    atomicAdd(&g_sums[curg * F2 + f], acc);
}

__global__ void k_cnts()
{
    int i = blockIdx.x * blockDim.x + threadIdx.x;
    if (i < NN) atomicAdd(&g_cnts[g_batch[i]], 1.0f);
}

// ---------------- heads ----------------
__global__ void k_head(const float* __restrict__ b2,
                       const float* __restrict__ Wg, const float* __restrict__ bg,
                       const float* __restrict__ Wf, const float* __restrict__ bf,
                       float* __restrict__ out)
{
    __shared__ float p[F2];
    int b = blockIdx.x, t = threadIdx.x;
    float cnt = g_cnts[b];
    float inv = 1.0f / fmaxf(cnt, 1.0f);
    p[t] = (cnt > 0.f) ? (g_sums[b * F2 + t] * inv + b2[t]) : 0.0f;
    __syncthreads();
    if (t < NGRP) {
        float a = bg[t];
        for (int d = 0; d < F2; d++) a += p[d] * Wg[d * NGRP + t];
        out[b * NGRP + t] = a;
    } else if (t >= 64 && t < 64 + NGRP * NFAM) {
        int u = t - 64;
        int grp = u / NFAM, f = u - grp * NFAM;
        float a = bf[grp * NFAM + f];
        for (int d = 0; d < F2; d++) a += p[d] * Wf[(size_t)grp * F2 * NFAM + d * NFAM + f];
        out[NG * NGRP + (size_t)grp * NG * NFAM + b * NFAM + f] = a;
    }
}

// ---------------- launch ----------------
extern "C" void kernel_launch(void* const* d_in, const int* in_sizes, int n_in,
                              void* d_out, int out_size)
{
    const float* x    = (const float*)d_in[0];
    const void*  eidx = d_in[1];
    const void*  batc = d_in[2];
    const float* W1   = (const float*)d_in[3];
    const float* b1   = (const float*)d_in[4];
    const float* W2   = (const float*)d_in[5];
    const float* b2   = (const float*)d_in[6];
    const float* Wg   = (const float*)d_in[7];
    const float* bg   = (const float*)d_in[8];
    const float* Wf   = (const float*)d_in[9];
    const float* bf   = (const float*)d_in[10];
    float* out = (float*)d_out;

    float *xw1, *agg1, *xw2, *agg2, *dinv;
    int *eidx32, *batch32;
    cudaGetSymbolAddress((void**)&xw1,  g_xw1);
    cudaGetSymbolAddress((void**)&agg1, g_agg1);
    cudaGetSymbolAddress((void**)&xw2,  g_xw2);
    cudaGetSymbolAddress((void**)&agg2, g_agg2);
    cudaGetSymbolAddress((void**)&dinv, g_dinv);
    cudaGetSymbolAddress((void**)&eidx32,  g_eidx);
    cudaGetSymbolAddress((void**)&batch32, g_batch);

    // 1) normalize index dtypes
    k_detect<<<1, 1>>>((const unsigned int*)eidx);
    k_convert<<<(2 * NE + 255) / 256, 256>>>((const int*)eidx, eidx32, 2 * NE);
    k_convert<<<(NN + 255) / 256, 256>>>((const int*)batc, batch32, NN);

    // 2) degree + dinv
    k_init<<<(NG * F2 + 255) / 256, 256>>>();
    k_deg_count<<<(NE + 255) / 256, 256>>>();
    k_dinv<<<(NN + 255) / 256, 256>>>();

    // 3) CSR build (dst-sorted)
    k_scan_local<<<NBLK, SB>>>();
    k_scan_bsum<<<1, 256>>>();
    k_scan_add<<<NBLK, SB>>>();
    k_fill<<<(NE + 255) / 256, 256>>>();

    // 4) layer 1
    {
        dim3 grid((NN + 63) / 64, F1 / 64);
        k_gemm<F1, false><<<grid, 256>>>(x, W1, nullptr, dinv, xw1, agg1, NN);
    }
    k_gather<F1><<<(NN * 32 + 255) / 256, 256>>>(xw1, agg1);

    // 5) layer 2 (relu(agg1+b1) fused into A-load)
    {
        dim3 grid((NN + 63) / 64, F2 / 64);
        k_gemm<F2, true><<<grid, 256>>>(agg1, W2, b1, dinv, xw2, agg2, NN);
    }
    k_gather<F2><<<(NN * 32 + 255) / 256, 256>>>(xw2, agg2);

    // 6) pool + heads
    k_pool<<<(NN + 63) / 64, 256>>>();
    k_cnts<<<(NN + 255) / 256, 256>>>();
    k_head<<<NG, 256>>>(b2, Wg, bg, Wf, bf, out);
}

// round 5
// speedup vs baseline: 2.9694x; 1.0837x over previous
#include <cuda_runtime.h>
#include <cuda_bf16.h>
#include <math.h>

// ---------------- problem constants ----------------
#define NN 100000          // nodes
#define NE 1600000         // edges
#define NG 512             // graphs
#define F1 128             // IN_F == H1
#define F2 256             // H2
#define NGRP 16
#define NFAM 10

#define SB 512
#define NBLK ((NN + SB - 1) / SB)   // 196 scan blocks

// init must cover max(NN, NG*F2, NG) = NG*F2 = 131072 entries
#define INIT_N (NG * F2)

// ---------------- device scratch (no allocations allowed) ----------------
__device__ float g_xw1 [ (size_t)NN * F1 ];   // x @ W1
__device__ float g_agg1[ (size_t)NN * F1 ];   // A_hat * xw1
__device__ float g_h2  [ (size_t)NN * F1 ];   // A_hat * relu(agg1+b1)
__device__ float g_out2[ (size_t)NN * F2 ];   // h2 @ W2
__device__ float g_dinv[ NN ];
__device__ float g_sums[ NG * F2 ];
__device__ float g_cnts[ NG ];
__device__ int   g_eidx[ 2 * NE ];     // [src(NE), dst(NE)] as int32
__device__ int   g_batch[ NN ];
__device__ int   g_is64;
__device__ int   g_degi  [ NN ];       // in-degree (no self loop)
__device__ int   g_off   [ NN ];       // CSR exclusive offsets
__device__ int   g_cursor[ NN ];
__device__ int   g_bsum  [ 256 ];
__device__ int   g_csr_src [ NE ];
__device__ float g_csr_coef[ NE ];

// ---------------- dtype detection + index normalization ----------------
__global__ void k_detect(const unsigned int* __restrict__ e) {
    int is64 = 1;
    for (int i = 0; i < 64; i++)
        if (e[2 * i + 1] != 0u) { is64 = 0; break; }
    g_is64 = is64;
}

__global__ void k_convert(const int* __restrict__ in, int* __restrict__ out, int n) {
    int i = blockIdx.x * blockDim.x + threadIdx.x;
    if (i >= n) return;
    out[i] = g_is64 ? in[2 * i] : in[i];
}

// ---------------- init / degree ----------------
// Grid MUST cover INIT_N threads: zeroes g_degi (NN), g_sums (NG*F2), g_cnts (NG).
__global__ void k_init() {
    int i = blockIdx.x * blockDim.x + threadIdx.x;
    if (i < NN) g_degi[i] = 0;
    if (i < NG * F2) g_sums[i] = 0.0f;
    if (i < NG) g_cnts[i] = 0.0f;
}

__global__ void k_deg_count() {
    int e = blockIdx.x * blockDim.x + threadIdx.x;
    if (e >= NE) return;
    atomicAdd(&g_degi[g_eidx[NE + e]], 1);       // dst
}

__global__ void k_dinv() {
    int i = blockIdx.x * blockDim.x + threadIdx.x;
    if (i < NN) g_dinv[i] = rsqrtf((float)(g_degi[i] + 1));
}

// ---------------- exclusive scan over g_degi -> g_off ----------------
__global__ void k_scan_local() {
    __shared__ int sh[SB];
    int i = blockIdx.x * SB + threadIdx.x;
    int v = (i < NN) ? g_degi[i] : 0;
    sh[threadIdx.x] = v;
    __syncthreads();
    for (int off = 1; off < SB; off <<= 1) {
        int t = (threadIdx.x >= off) ? sh[threadIdx.x - off] : 0;
        __syncthreads();
        sh[threadIdx.x] += t;
        __syncthreads();
    }
    if (i < NN) g_off[i] = sh[threadIdx.x] - v;   // exclusive
    if (threadIdx.x == SB - 1) g_bsum[blockIdx.x] = sh[SB - 1];
}

__global__ void k_scan_bsum() {
    __shared__ int sh[256];
    int t = threadIdx.x;
    int v = (t < NBLK) ? g_bsum[t] : 0;
    sh[t] = v;
    __syncthreads();
    for (int off = 1; off < 256; off <<= 1) {
        int u = (t >= off) ? sh[t - off] : 0;
        __syncthreads();
        sh[t] += u;
        __syncthreads();
    }
    if (t < NBLK) g_bsum[t] = sh[t] - v;          // exclusive
}

__global__ void k_scan_add() {
    int i = blockIdx.x * SB + threadIdx.x;
    if (i < NN) {
        int o = g_off[i] + g_bsum[blockIdx.x];
        g_off[i] = o;
        g_cursor[i] = o;
    }
}

// ---------------- CSR fill: per-dst segments of (src, coef) ----------------
__global__ void k_fill() {
    int e = blockIdx.x * blockDim.x + threadIdx.x;
    if (e >= NE) return;
    int s = g_eidx[e];
    int d = g_eidx[NE + e];
    int slot = atomicAdd(&g_cursor[d], 1);
    g_csr_src[slot] = s;
    g_csr_coef[slot] = g_dinv[s] * g_dinv[d];
}

// ---------------- fp32 tiled GEMM: C[M,N] = A[M,128] * B[128,N] (plain) ----------
template<int N>
__launch_bounds__(256)
__global__ void k_gemm(const float* __restrict__ A, const float* __restrict__ B,
                       float* __restrict__ C, int M)
{
    __shared__ float As[64][65];
    __shared__ float Bs[64][64];

    const int tid  = threadIdx.x;
    const int tx   = tid & 15;
    const int ty   = tid >> 4;
    const int row0 = blockIdx.x * 64;
    const int col0 = blockIdx.y * 64;

    float acc[4][4];
#pragma unroll
    for (int i = 0; i < 4; i++)
#pragma unroll
        for (int j = 0; j < 4; j++) acc[i][j] = 0.0f;

    for (int kh = 0; kh < 2; kh++) {
#pragma unroll
        for (int it = 0; it < 4; it++) {
            int i  = tid + it * 256;
            int m  = i >> 4;
            int k4 = i & 15;
            int row = row0 + m;
            float4 v = make_float4(0.f, 0.f, 0.f, 0.f);
            if (row < M)
                v = *(const float4*)(A + (size_t)row * 128 + kh * 64 + k4 * 4);
            As[m][k4 * 4 + 0] = v.x;
            As[m][k4 * 4 + 1] = v.y;
            As[m][k4 * 4 + 2] = v.z;
            As[m][k4 * 4 + 3] = v.w;
        }
#pragma unroll
        for (int it = 0; it < 4; it++) {
            int i  = tid + it * 256;
            int k  = i >> 4;
            int n4 = i & 15;
            *(float4*)(&Bs[k][n4 * 4]) =
                *(const float4*)(B + (size_t)(kh * 64 + k) * N + col0 + n4 * 4);
        }
        __syncthreads();

#pragma unroll 8
        for (int k = 0; k < 64; k++) {
            float a0 = As[tx     ][k];
            float a1 = As[tx + 16][k];
            float a2 = As[tx + 32][k];
            float a3 = As[tx + 48][k];
            float4 b = *(const float4*)(&Bs[k][ty * 4]);
            acc[0][0] += a0 * b.x; acc[0][1] += a0 * b.y; acc[0][2] += a0 * b.z; acc[0][3] += a0 * b.w;
            acc[1][0] += a1 * b.x; acc[1][1] += a1 * b.y; acc[1][2] += a1 * b.z; acc[1][3] += a1 * b.w;
            acc[2][0] += a2 * b.x; acc[2][1] += a2 * b.y; acc[2][2] += a2 * b.z; acc[2][3] += a2 * b.w;
            acc[3][0] += a3 * b.x; acc[3][1] += a3 * b.y; acc[3][2] += a3 * b.z; acc[3][3] += a3 * b.w;
        }
        __syncthreads();
    }

#pragma unroll
    for (int i = 0; i < 4; i++) {
        int row = row0 + tx + 16 * i;
        if (row < M) {
            size_t off = (size_t)row * N + col0 + ty * 4;
            *(float4*)(C + off) = make_float4(acc[i][0], acc[i][1], acc[i][2], acc[i][3]);
        }
    }
}

// ---------------- CSR gather over F=128, self-loop folded in ----------------
// out[d] = sum_e coef_e * f(in[src_e]) + dinv[d]^2 * f(in[d]),
// f(v) = RELU ? max(v + b1, 0) : v.  One warp per dst; lane owns one float4.
template<bool RELU>
__launch_bounds__(256)
__global__ void k_gather(const float* __restrict__ in, const float* __restrict__ bias,
                         float* __restrict__ out)
{
    int d = (blockIdx.x * 256 + threadIdx.x) >> 5;
    if (d >= NN) return;
    int lane = threadIdx.x & 31;
    int beg = g_off[d];
    int end = beg + g_degi[d];

    float4 bb = make_float4(0.f, 0.f, 0.f, 0.f);
    if (RELU) bb = *(const float4*)(bias + lane * 4);

    float4 acc = make_float4(0.f, 0.f, 0.f, 0.f);

    int j = beg;
    for (; j + 1 < end; j += 2) {
        int   s0 = g_csr_src[j],  s1 = g_csr_src[j + 1];
        float c0 = g_csr_coef[j], c1 = g_csr_coef[j + 1];
        float4 v0 = *(const float4*)(in + (size_t)s0 * 128 + lane * 4);
        float4 v1 = *(const float4*)(in + (size_t)s1 * 128 + lane * 4);
        if (RELU) {
            v0.x = fmaxf(v0.x + bb.x, 0.f); v0.y = fmaxf(v0.y + bb.y, 0.f);
            v0.z = fmaxf(v0.z + bb.z, 0.f); v0.w = fmaxf(v0.w + bb.w, 0.f);
            v1.x = fmaxf(v1.x + bb.x, 0.f); v1.y = fmaxf(v1.y + bb.y, 0.f);
            v1.z = fmaxf(v1.z + bb.z, 0.f); v1.w = fmaxf(v1.w + bb.w, 0.f);
        }
        acc.x += c0 * v0.x + c1 * v1.x;
        acc.y += c0 * v0.y + c1 * v1.y;
        acc.z += c0 * v0.z + c1 * v1.z;
        acc.w += c0 * v0.w + c1 * v1.w;
    }
    if (j < end) {
        int   s0 = g_csr_src[j];
        float c0 = g_csr_coef[j];
        float4 v0 = *(const float4*)(in + (size_t)s0 * 128 + lane * 4);
        if (RELU) {
            v0.x = fmaxf(v0.x + bb.x, 0.f); v0.y = fmaxf(v0.y + bb.y, 0.f);
            v0.z = fmaxf(v0.z + bb.z, 0.f); v0.w = fmaxf(v0.w + bb.w, 0.f);
        }
        acc.x += c0 * v0.x; acc.y += c0 * v0.y;
        acc.z += c0 * v0.z; acc.w += c0 * v0.w;
    }

    // self loop
    {
        float dv = g_dinv[d];
        float c = dv * dv;
        float4 v = *(const float4*)(in + (size_t)d * 128 + lane * 4);
        if (RELU) {
            v.x = fmaxf(v.x + bb.x, 0.f); v.y = fmaxf(v.y + bb.y, 0.f);
            v.z = fmaxf(v.z + bb.z, 0.f); v.w = fmaxf(v.w + bb.w, 0.f);
        }
        acc.x += c * v.x; acc.y += c * v.y;
        acc.z += c * v.z; acc.w += c * v.w;
    }

    *(float4*)(out + (size_t)d * 128 + lane * 4) = acc;
}

// ---------------- pooling (batch sorted -> register accumulation) ----------------
__global__ void k_pool()
{
    int f  = threadIdx.x;                        // 256 = F2
    int n0 = blockIdx.x * 64;
    int n1 = min(n0 + 64, NN);
    if (n0 >= NN) return;
    int curg = g_batch[n0];
    float acc = 0.0f;
    for (int n = n0; n < n1; n++) {
        int gg = g_batch[n];
        if (gg != curg) {
            atomicAdd(&g_sums[curg * F2 + f], acc);
            acc = 0.0f; curg = gg;
        }
        acc += g_out2[(size_t)n * F2 + f];
    }
    atomicAdd(&g_sums[curg * F2 + f], acc);
}

__global__ void k_cnts()
{
    int i = blockIdx.x * blockDim.x + threadIdx.x;
    if (i < NN) atomicAdd(&g_cnts[g_batch[i]], 1.0f);
}

// ---------------- heads ----------------
__global__ void k_head(const float* __restrict__ b2,
                       const float* __restrict__ Wg, const float* __restrict__ bg,
                       const float* __restrict__ Wf, const float* __restrict__ bf,
                       float* __restrict__ out)
{
    __shared__ float p[F2];
    int b = blockIdx.x, t = threadIdx.x;
    float cnt = g_cnts[b];
    float inv = 1.0f / fmaxf(cnt, 1.0f);
    p[t] = (cnt > 0.f) ? (g_sums[b * F2 + t] * inv + b2[t]) : 0.0f;
    __syncthreads();
    if (t < NGRP) {
        float a = bg[t];
        for (int d = 0; d < F2; d++) a += p[d] * Wg[d * NGRP + t];
        out[b * NGRP + t] = a;
    } else if (t >= 64 && t < 64 + NGRP * NFAM) {
        int u = t - 64;
        int grp = u / NFAM, f = u - grp * NFAM;
        float a = bf[grp * NFAM + f];
        for (int d = 0; d < F2; d++) a += p[d] * Wf[(size_t)grp * F2 * NFAM + d * NFAM + f];
        out[NG * NGRP + (size_t)grp * NG * NFAM + b * NFAM + f] = a;
    }
}

// ---------------- launch ----------------
extern "C" void kernel_launch(void* const* d_in, const int* in_sizes, int n_in,
                              void* d_out, int out_size)
{
    const float* x    = (const float*)d_in[0];
    const void*  eidx = d_in[1];
    const void*  batc = d_in[2];
    const float* W1   = (const float*)d_in[3];
    const float* b1   = (const float*)d_in[4];
    const float* W2   = (const float*)d_in[5];
    const float* b2   = (const float*)d_in[6];
    const float* Wg   = (const float*)d_in[7];
    const float* bg   = (const float*)d_in[8];
    const float* Wf   = (const float*)d_in[9];
    const float* bf   = (const float*)d_in[10];
    float* out = (float*)d_out;

    float *xw1, *agg1, *h2, *out2;
    int *eidx32, *batch32;
    cudaGetSymbolAddress((void**)&xw1,  g_xw1);
    cudaGetSymbolAddress((void**)&agg1, g_agg1);
    cudaGetSymbolAddress((void**)&h2,   g_h2);
    cudaGetSymbolAddress((void**)&out2, g_out2);
    cudaGetSymbolAddress((void**)&eidx32,  g_eidx);
    cudaGetSymbolAddress((void**)&batch32, g_batch);

    // launches 0..2: normalize index dtypes
    k_detect<<<1, 1>>>((const unsigned int*)eidx);
    k_convert<<<(2 * NE + 255) / 256, 256>>>((const int*)eidx, eidx32, 2 * NE);
    k_convert<<<(NN + 255) / 256, 256>>>((const int*)batc, batch32, NN);

    // launch 3 (ncu-profiled slot): GEMM1  xw1 = x @ W1   (no graph deps)
    {
        dim3 grid((NN + 63) / 64, F1 / 64);
        k_gemm<F1><<<grid, 256>>>(x, W1, xw1, NN);
    }

    // degree + dinv  (init covers NG*F2 = 131072 >= NN threads)
    k_init<<<(INIT_N + 255) / 256, 256>>>();
    k_deg_count<<<(NE + 255) / 256, 256>>>();
    k_dinv<<<(NN + 255) / 256, 256>>>();

    // CSR build (dst-sorted)
    k_scan_local<<<NBLK, SB>>>();
    k_scan_bsum<<<1, 256>>>();
    k_scan_add<<<NBLK, SB>>>();
    k_fill<<<(NE + 255) / 256, 256>>>();

    // layer 1 aggregate: agg1 = A_hat * xw1
    k_gather<false><<<(NN * 32 + 255) / 256, 256>>>(xw1, nullptr, agg1);

    // layer 2 aggregate-first: h2 = A_hat * relu(agg1 + b1)
    k_gather<true><<<(NN * 32 + 255) / 256, 256>>>(agg1, b1, h2);

    // GEMM2: out2 = h2 @ W2
    {
        dim3 grid((NN + 63) / 64, F2 / 64);
        k_gemm<F2><<<grid, 256>>>(h2, W2, out2, NN);
    }

    // pool + heads (b2 folded into head)
    k_pool<<<(NN + 63) / 64, 256>>>();
    k_cnts<<<(NN + 255) / 256, 256>>>();
    k_head<<<NG, 256>>>(b2, Wg, bg, Wf, bf, out);
}

// round 6
// speedup vs baseline: 5.3137x; 1.7895x over previous
#include <cuda_runtime.h>
#include <cuda_bf16.h>
#include <math.h>

// ---------------- problem constants ----------------
#define NN 100000          // nodes
#define NE 1600000         // edges
#define NG 512             // graphs
#define F1 128             // IN_F == H1
#define F2 256             // H2
#define NGRP 16
#define NFAM 10

#define SB 512
#define NBLK ((NN + SB - 1) / SB)   // 196 scan blocks

// init must cover max(NN, NG*F2) = 131072 entries
#define INIT_N (NG * F2)

// ---------------- device scratch (no allocations allowed) ----------------
__device__ float g_xw1 [ (size_t)NN * F1 ];   // x @ W1
__device__ float g_r1  [ (size_t)NN * F1 ];   // relu(A_hat*xw1 + b1)
__device__ float g_h2  [ (size_t)NN * F1 ];   // A_hat * r1
__device__ float g_psum[ NG * F1 ];           // per-graph sum of h2
__device__ float g_pooled2[ NG * F2 ];        // pooled @ W2 + b2
__device__ float g_dinv[ NN ];
__device__ float g_cnts[ NG ];
__device__ int   g_eidx[ 2 * NE ];            // [src(NE), dst(NE)] as int32
__device__ int   g_batch[ NN ];
__device__ int   g_is64;
__device__ int   g_degi  [ NN ];              // in-degree (no self loop)
__device__ int   g_off   [ NN ];              // CSR exclusive offsets
__device__ int   g_cursor[ NN ];
__device__ int   g_bsum  [ 256 ];
__device__ int   g_csr_src [ NE ];
__device__ float g_csr_coef[ NE ];

// ---------------- dtype detection + index normalization ----------------
__global__ void k_detect(const unsigned int* __restrict__ e) {
    int is64 = 1;
    for (int i = 0; i < 64; i++)
        if (e[2 * i + 1] != 0u) { is64 = 0; break; }
    g_is64 = is64;
}

__global__ void k_convert(const int* __restrict__ in, int* __restrict__ out, int n) {
    int i = blockIdx.x * blockDim.x + threadIdx.x;
    if (i >= n) return;
    out[i] = g_is64 ? in[2 * i] : in[i];
}

// ---------------- init / degree ----------------
// Grid covers INIT_N threads: zeroes g_degi (NN), g_psum (NG*F1), g_cnts (NG).
__global__ void k_init() {
    int i = blockIdx.x * blockDim.x + threadIdx.x;
    if (i < NN) g_degi[i] = 0;
    if (i < NG * F1) g_psum[i] = 0.0f;
    if (i < NG) g_cnts[i] = 0.0f;
}

__global__ void k_deg_count() {
    int e = blockIdx.x * blockDim.x + threadIdx.x;
    if (e >= NE) return;
    atomicAdd(&g_degi[g_eidx[NE + e]], 1);       // dst
}

__global__ void k_dinv() {
    int i = blockIdx.x * blockDim.x + threadIdx.x;
    if (i < NN) g_dinv[i] = rsqrtf((float)(g_degi[i] + 1));
}

// ---------------- exclusive scan over g_degi -> g_off ----------------
__global__ void k_scan_local() {
    __shared__ int sh[SB];
    int i = blockIdx.x * SB + threadIdx.x;
    int v = (i < NN) ? g_degi[i] : 0;
    sh[threadIdx.x] = v;
    __syncthreads();
    for (int off = 1; off < SB; off <<= 1) {
        int t = (threadIdx.x >= off) ? sh[threadIdx.x - off] : 0;
        __syncthreads();
        sh[threadIdx.x] += t;
        __syncthreads();
    }
    if (i < NN) g_off[i] = sh[threadIdx.x] - v;   // exclusive
    if (threadIdx.x == SB - 1) g_bsum[blockIdx.x] = sh[SB - 1];
}

__global__ void k_scan_bsum() {
    __shared__ int sh[256];
    int t = threadIdx.x;
    int v = (t < NBLK) ? g_bsum[t] : 0;
    sh[t] = v;
    __syncthreads();
    for (int off = 1; off < 256; off <<= 1) {
        int u = (t >= off) ? sh[t - off] : 0;
        __syncthreads();
        sh[t] += u;
        __syncthreads();
    }
    if (t < NBLK) g_bsum[t] = sh[t] - v;          // exclusive
}

__global__ void k_scan_add() {
    int i = blockIdx.x * SB + threadIdx.x;
    if (i < NN) {
        int o = g_off[i] + g_bsum[blockIdx.x];
        g_off[i] = o;
        g_cursor[i] = o;
    }
}

// ---------------- CSR fill: per-dst segments of (src, coef) ----------------
__global__ void k_fill() {
    int e = blockIdx.x * blockDim.x + threadIdx.x;
    if (e >= NE) return;
    int s = g_eidx[e];
    int d = g_eidx[NE + e];
    int slot = atomicAdd(&g_cursor[d], 1);
    g_csr_src[slot] = s;
    g_csr_coef[slot] = g_dinv[s] * g_dinv[d];
}

// ---------------- GEMM1: C[M,128] = A[M,128] * B[128,128] ----------------
// BM=128, BN=128, BK=16, 256 threads, 8x8 per thread, all-float4 LDS.
__launch_bounds__(256)
__global__ void k_gemm1(const float* __restrict__ A, const float* __restrict__ B,
                        float* __restrict__ C, int M)
{
    __shared__ float As[16][132];   // transposed: As[k][m]
    __shared__ float Bs[16][128];

    const int tid  = threadIdx.x;
    const int ty   = tid >> 4;      // 0..15 -> row group
    const int tx   = tid & 15;      // 0..15 -> col group
    const int row0 = blockIdx.x * 128;

    float acc[8][8];
#pragma unroll
    for (int i = 0; i < 8; i++)
#pragma unroll
        for (int j = 0; j < 8; j++) acc[i][j] = 0.0f;

    for (int kc = 0; kc < 128; kc += 16) {
        // stage A (transposed): 128 m x 16 k = 512 float4 slots, 2/thread
#pragma unroll
        for (int it = 0; it < 2; it++) {
            int s  = tid + it * 256;
            int m  = s >> 2;
            int k4 = s & 3;
            int row = row0 + m;
            float4 v = make_float4(0.f, 0.f, 0.f, 0.f);
            if (row < M)
                v = *(const float4*)(A + (size_t)row * 128 + kc + k4 * 4);
            As[k4 * 4 + 0][m] = v.x;
            As[k4 * 4 + 1][m] = v.y;
            As[k4 * 4 + 2][m] = v.z;
            As[k4 * 4 + 3][m] = v.w;
        }
        // stage B: 16 k x 128 n = 512 float4 slots, 2/thread
#pragma unroll
        for (int it = 0; it < 2; it++) {
            int s  = tid + it * 256;
            int k  = s >> 5;
            int n4 = s & 31;
            *(float4*)(&Bs[k][n4 * 4]) =
                *(const float4*)(B + (size_t)(kc + k) * 128 + n4 * 4);
        }
        __syncthreads();

#pragma unroll
        for (int k = 0; k < 16; k++) {
            float a[8], b[8];
            *(float4*)(a)     = *(const float4*)(&As[k][ty * 8]);
            *(float4*)(a + 4) = *(const float4*)(&As[k][ty * 8 + 4]);
            *(float4*)(b)     = *(const float4*)(&Bs[k][tx * 8]);
            *(float4*)(b + 4) = *(const float4*)(&Bs[k][tx * 8 + 4]);
#pragma unroll
            for (int i = 0; i < 8; i++)
#pragma unroll
                for (int j = 0; j < 8; j++)
                    acc[i][j] += a[i] * b[j];
        }
        __syncthreads();
    }

#pragma unroll
    for (int i = 0; i < 8; i++) {
        int row = row0 + ty * 8 + i;
        if (row < M) {
            *(float4*)(C + (size_t)row * 128 + tx * 8) =
                make_float4(acc[i][0], acc[i][1], acc[i][2], acc[i][3]);
            *(float4*)(C + (size_t)row * 128 + tx * 8 + 4) =
                make_float4(acc[i][4], acc[i][5], acc[i][6], acc[i][7]);
        }
    }
}

// ---------------- CSR gather over F=128, self-loop folded in ----------------
// acc[d] = sum_e coef_e * in[src_e] + dinv[d]^2 * in[d]
// RELU_OUT: store relu(acc + b1); else store acc.
// One warp per dst; lane owns one float4.
template<bool RELU_OUT>
__launch_bounds__(256)
__global__ void k_gather(const float* __restrict__ in, const float* __restrict__ bias,
                         float* __restrict__ out)
{
    int d = (blockIdx.x * 256 + threadIdx.x) >> 5;
    if (d >= NN) return;
    int lane = threadIdx.x & 31;
    int beg = g_off[d];
    int end = beg + g_degi[d];

    float4 acc = make_float4(0.f, 0.f, 0.f, 0.f);

    int j = beg;
    for (; j + 3 < end; j += 4) {
        int   s0 = g_csr_src[j],      s1 = g_csr_src[j + 1];
        int   s2 = g_csr_src[j + 2],  s3 = g_csr_src[j + 3];
        float c0 = g_csr_coef[j],     c1 = g_csr_coef[j + 1];
        float c2 = g_csr_coef[j + 2], c3 = g_csr_coef[j + 3];
        float4 v0 = *(const float4*)(in + (size_t)s0 * 128 + lane * 4);
        float4 v1 = *(const float4*)(in + (size_t)s1 * 128 + lane * 4);
        float4 v2 = *(const float4*)(in + (size_t)s2 * 128 + lane * 4);
        float4 v3 = *(const float4*)(in + (size_t)s3 * 128 + lane * 4);
        acc.x += c0 * v0.x + c1 * v1.x + c2 * v2.x + c3 * v3.x;
        acc.y += c0 * v0.y + c1 * v1.y + c2 * v2.y + c3 * v3.y;
        acc.z += c0 * v0.z + c1 * v1.z + c2 * v2.z + c3 * v3.z;
        acc.w += c0 * v0.w + c1 * v1.w + c2 * v2.w + c3 * v3.w;
    }
    for (; j < end; j++) {
        int   s0 = g_csr_src[j];
        float c0 = g_csr_coef[j];
        float4 v0 = *(const float4*)(in + (size_t)s0 * 128 + lane * 4);
        acc.x += c0 * v0.x; acc.y += c0 * v0.y;
        acc.z += c0 * v0.z; acc.w += c0 * v0.w;
    }

    // self loop
    {
        float dv = g_dinv[d];
        float c = dv * dv;
        float4 v = *(const float4*)(in + (size_t)d * 128 + lane * 4);
        acc.x += c * v.x; acc.y += c * v.y;
        acc.z += c * v.z; acc.w += c * v.w;
    }

    if (RELU_OUT) {
        float4 bb = *(const float4*)(bias + lane * 4);
        acc.x = fmaxf(acc.x + bb.x, 0.f);
        acc.y = fmaxf(acc.y + bb.y, 0.f);
        acc.z = fmaxf(acc.z + bb.z, 0.f);
        acc.w = fmaxf(acc.w + bb.w, 0.f);
    }

    *(float4*)(out + (size_t)d * 128 + lane * 4) = acc;
}

// ---------------- pooling over h2 (F=128; batch sorted) ----------------
__global__ void k_pool()
{
    int f  = threadIdx.x;                        // 128 = F1
    int n0 = blockIdx.x * 64;
    int n1 = min(n0 + 64, NN);
    if (n0 >= NN) return;
    int curg = g_batch[n0];
    float acc = 0.0f;
    for (int n = n0; n < n1; n++) {
        int gg = g_batch[n];
        if (gg != curg) {
            atomicAdd(&g_psum[curg * F1 + f], acc);
            acc = 0.0f; curg = gg;
        }
        acc += g_h2[(size_t)n * F1 + f];
    }
    atomicAdd(&g_psum[curg * F1 + f], acc);
}

__global__ void k_cnts()
{
    int i = blockIdx.x * blockDim.x + threadIdx.x;
    if (i < NN) atomicAdd(&g_cnts[g_batch[i]], 1.0f);
}

// ---------------- pooled @ W2 + b2  -> g_pooled2 [NG, 256] ----------------
__global__ void k_w2pool(const float* __restrict__ W2, const float* __restrict__ b2)
{
    __shared__ float p[F1];
    int b = blockIdx.x, t = threadIdx.x;         // 256 threads
    float cnt = g_cnts[b];
    float inv = 1.0f / fmaxf(cnt, 1.0f);
    if (t < F1) p[t] = (cnt > 0.f) ? g_psum[b * F1 + t] * inv : 0.0f;
    __syncthreads();
    float a = (cnt > 0.f) ? b2[t] : 0.0f;
#pragma unroll 4
    for (int d = 0; d < F1; d++) a += p[d] * W2[d * F2 + t];
    g_pooled2[b * F2 + t] = a;
}

// ---------------- heads ----------------
// out[0 : 512*16)           = group_logits  [G, 16]
// out[8192 : 8192+16*512*10) = family_logits [16, G, 10]
__global__ void k_head(const float* __restrict__ Wg, const float* __restrict__ bg,
                       const float* __restrict__ Wf, const float* __restrict__ bf,
                       float* __restrict__ out)
{
    __shared__ float p[F2];
    int b = blockIdx.x, t = threadIdx.x;
    p[t] = g_pooled2[b * F2 + t];
    __syncthreads();
    if (t < NGRP) {
        float a = bg[t];
        for (int d = 0; d < F2; d++) a += p[d] * Wg[d * NGRP + t];
        out[b * NGRP + t] = a;
    } else if (t >= 64 && t < 64 + NGRP * NFAM) {
        int u = t - 64;
        int grp = u / NFAM, f = u - grp * NFAM;
        float a = bf[grp * NFAM + f];
        for (int d = 0; d < F2; d++) a += p[d] * Wf[(size_t)grp * F2 * NFAM + d * NFAM + f];
        out[NG * NGRP + (size_t)grp * NG * NFAM + b * NFAM + f] = a;
    }
}

// ---------------- launch ----------------
extern "C" void kernel_launch(void* const* d_in, const int* in_sizes, int n_in,
                              void* d_out, int out_size)
{
    const float* x    = (const float*)d_in[0];
    const void*  eidx = d_in[1];
    const void*  batc = d_in[2];
    const float* W1   = (const float*)d_in[3];
    const float* b1   = (const float*)d_in[4];
    const float* W2   = (const float*)d_in[5];
    const float* b2   = (const float*)d_in[6];
    const float* Wg   = (const float*)d_in[7];
    const float* bg   = (const float*)d_in[8];
    const float* Wf   = (const float*)d_in[9];
    const float* bf   = (const float*)d_in[10];
    float* out = (float*)d_out;

    float *xw1, *r1, *h2;
    int *eidx32, *batch32;
    cudaGetSymbolAddress((void**)&xw1, g_xw1);
    cudaGetSymbolAddress((void**)&r1,  g_r1);
    cudaGetSymbolAddress((void**)&h2,  g_h2);
    cudaGetSymbolAddress((void**)&eidx32,  g_eidx);
    cudaGetSymbolAddress((void**)&batch32, g_batch);

    // launches 1..3: normalize index dtypes
    k_detect<<<1, 1>>>((const unsigned int*)eidx);
    k_convert<<<(2 * NE + 255) / 256, 256>>>((const int*)eidx, eidx32, 2 * NE);
    k_convert<<<(NN + 255) / 256, 256>>>((const int*)batc, batch32, NN);

    // launch 4 (ncu-profiled slot): GEMM1  xw1 = x @ W1
    k_gemm1<<<(NN + 127) / 128, 256>>>(x, W1, xw1, NN);

    // degree + dinv  (init covers 131072 threads)
    k_init<<<(INIT_N + 255) / 256, 256>>>();
    k_deg_count<<<(NE + 255) / 256, 256>>>();
    k_dinv<<<(NN + 255) / 256, 256>>>();

    // CSR build (dst-sorted)
    k_scan_local<<<NBLK, SB>>>();
    k_scan_bsum<<<1, 256>>>();
    k_scan_add<<<NBLK, SB>>>();
    k_fill<<<(NE + 255) / 256, 256>>>();

    // layer 1 aggregate + relu:  r1 = relu(A_hat*xw1 + b1)
    k_gather<true><<<(NN * 32 + 255) / 256, 256>>>(xw1, b1, r1);

    // layer 2 aggregate: h2 = A_hat * r1
    k_gather<false><<<(NN * 32 + 255) / 256, 256>>>(r1, nullptr, h2);

    // pool h2 per graph, then tiny GEMM (pooled @ W2 + b2), then heads
    k_pool<<<(NN + 63) / 64, 128>>>();
    k_cnts<<<(NN + 255) / 256, 256>>>();
    k_w2pool<<<NG, 256>>>(W2, b2);
    k_head<<<NG, 256>>>(Wg, bg, Wf, bf, out);
}

// round 7
// speedup vs baseline: 5.8762x; 1.1059x over previous
#include <cuda_runtime.h>
#include <cuda_bf16.h>
#include <cuda_fp16.h>
#include <math.h>

// ---------------- problem constants ----------------
#define NN 100000          // nodes
#define NE 1600000         // edges
#define NG 512             // graphs
#define F1 128             // IN_F == H1
#define F2 256             // H2
#define NGRP 16
#define NFAM 10

#define SB 512
#define NBLK ((NN + SB - 1) / SB)   // 196 scan blocks

// init must cover max(NN, NG*F1, NG) entries
#define INIT_N (NG * F2)

// ---------------- device scratch (no allocations allowed) ----------------
__device__ __half g_xw1h[ (size_t)NN * F1 ];  // x @ W1          (fp16 storage)
__device__ __half g_r1h [ (size_t)NN * F1 ];  // relu(A*xw1+b1)  (fp16 storage)
__device__ float  g_h2  [ (size_t)NN * F1 ];  // A_hat * r1      (fp32)
__device__ float  g_psum[ NG * F1 ];          // per-graph sum of h2
__device__ float  g_pooled2[ NG * F2 ];       // pooled @ W2 + b2
__device__ float  g_dinv[ NN ];
__device__ float  g_cnts[ NG ];
__device__ int    g_eidx[ 2 * NE ];           // [src(NE), dst(NE)] as int32
__device__ int    g_batch[ NN ];
__device__ int    g_is64;
__device__ int    g_degi  [ NN ];             // in-degree (no self loop)
__device__ int    g_off   [ NN ];             // CSR exclusive offsets
__device__ int    g_cursor[ NN ];
__device__ int    g_bsum  [ 256 ];
__device__ int    g_csr_src [ NE ];
__device__ float  g_csr_coef[ NE ];

// ---------------- dtype detection + index normalization ----------------
__global__ void k_detect(const unsigned int* __restrict__ e) {
    int is64 = 1;
    for (int i = 0; i < 64; i++)
        if (e[2 * i + 1] != 0u) { is64 = 0; break; }
    g_is64 = is64;
}

__global__ void k_convert(const int* __restrict__ in, int* __restrict__ out, int n) {
    int i = blockIdx.x * blockDim.x + threadIdx.x;
    if (i >= n) return;
    out[i] = g_is64 ? in[2 * i] : in[i];
}

// ---------------- init / degree ----------------
__global__ void k_init() {
    int i = blockIdx.x * blockDim.x + threadIdx.x;
    if (i < NN) g_degi[i] = 0;
    if (i < NG * F1) g_psum[i] = 0.0f;
    if (i < NG) g_cnts[i] = 0.0f;
}

__global__ void k_deg_count() {
    int e = blockIdx.x * blockDim.x + threadIdx.x;
    if (e >= NE) return;
    atomicAdd(&g_degi[g_eidx[NE + e]], 1);       // dst
}

__global__ void k_dinv() {
    int i = blockIdx.x * blockDim.x + threadIdx.x;
    if (i < NN) g_dinv[i] = rsqrtf((float)(g_degi[i] + 1));
}

// ---------------- exclusive scan over g_degi -> g_off ----------------
__global__ void k_scan_local() {
    __shared__ int sh[SB];
    int i = blockIdx.x * SB + threadIdx.x;
    int v = (i < NN) ? g_degi[i] : 0;
    sh[threadIdx.x] = v;
    __syncthreads();
    for (int off = 1; off < SB; off <<= 1) {
        int t = (threadIdx.x >= off) ? sh[threadIdx.x - off] : 0;
        __syncthreads();
        sh[threadIdx.x] += t;
        __syncthreads();
    }
    if (i < NN) g_off[i] = sh[threadIdx.x] - v;   // exclusive
    if (threadIdx.x == SB - 1) g_bsum[blockIdx.x] = sh[SB - 1];
}

__global__ void k_scan_bsum() {
    __shared__ int sh[256];
    int t = threadIdx.x;
    int v = (t < NBLK) ? g_bsum[t] : 0;
    sh[t] = v;
    __syncthreads();
    for (int off = 1; off < 256; off <<= 1) {
        int u = (t >= off) ? sh[t - off] : 0;
        __syncthreads();
        sh[t] += u;
        __syncthreads();
    }
    if (t < NBLK) g_bsum[t] = sh[t] - v;          // exclusive
}

__global__ void k_scan_add() {
    int i = blockIdx.x * SB + threadIdx.x;
    if (i < NN) {
        int o = g_off[i] + g_bsum[blockIdx.x];
        g_off[i] = o;
        g_cursor[i] = o;
    }
}

// ---------------- CSR fill: per-dst segments of (src, coef) ----------------
__global__ void k_fill() {
    int e = blockIdx.x * blockDim.x + threadIdx.x;
    if (e >= NE) return;
    int s = g_eidx[e];
    int d = g_eidx[NE + e];
    int slot = atomicAdd(&g_cursor[d], 1);
    g_csr_src[slot] = s;
    g_csr_coef[slot] = g_dinv[s] * g_dinv[d];
}

// ---------------- GEMM1: C[M,128] = A[M,128] * B[128,128] -> fp16 C ----------
// BM=128, BN=128, BK=16, 256 threads, 8x8 per thread, all-float4 LDS.
__launch_bounds__(256)
__global__ void k_gemm1(const float* __restrict__ A, const float* __restrict__ B,
                        __half* __restrict__ C, int M)
{
    __shared__ float As[16][132];   // transposed: As[k][m]
    __shared__ float Bs[16][128];

    const int tid  = threadIdx.x;
    const int ty   = tid >> 4;      // 0..15 -> row group
    const int tx   = tid & 15;      // 0..15 -> col group
    const int row0 = blockIdx.x * 128;

    float acc[8][8];
#pragma unroll
    for (int i = 0; i < 8; i++)
#pragma unroll
        for (int j = 0; j < 8; j++) acc[i][j] = 0.0f;

    for (int kc = 0; kc < 128; kc += 16) {
#pragma unroll
        for (int it = 0; it < 2; it++) {
            int s  = tid + it * 256;
            int m  = s >> 2;
            int k4 = s & 3;
            int row = row0 + m;
            float4 v = make_float4(0.f, 0.f, 0.f, 0.f);
            if (row < M)
                v = *(const float4*)(A + (size_t)row * 128 + kc + k4 * 4);
            As[k4 * 4 + 0][m] = v.x;
            As[k4 * 4 + 1][m] = v.y;
            As[k4 * 4 + 2][m] = v.z;
            As[k4 * 4 + 3][m] = v.w;
        }
#pragma unroll
        for (int it = 0; it < 2; it++) {
            int s  = tid + it * 256;
            int k  = s >> 5;
            int n4 = s & 31;
            *(float4*)(&Bs[k][n4 * 4]) =
                *(const float4*)(B + (size_t)(kc + k) * 128 + n4 * 4);
        }
        __syncthreads();

#pragma unroll
        for (int k = 0; k < 16; k++) {
            float a[8], b[8];
            *(float4*)(a)     = *(const float4*)(&As[k][ty * 8]);
            *(float4*)(a + 4) = *(const float4*)(&As[k][ty * 8 + 4]);
            *(float4*)(b)     = *(const float4*)(&Bs[k][tx * 8]);
            *(float4*)(b + 4) = *(const float4*)(&Bs[k][tx * 8 + 4]);
#pragma unroll
            for (int i = 0; i < 8; i++)
#pragma unroll
                for (int j = 0; j < 8; j++)
                    acc[i][j] += a[i] * b[j];
        }
        __syncthreads();
    }

#pragma unroll
    for (int i = 0; i < 8; i++) {
        int row = row0 + ty * 8 + i;
        if (row < M) {
            __half2 h0 = __floats2half2_rn(acc[i][0], acc[i][1]);
            __half2 h1 = __floats2half2_rn(acc[i][2], acc[i][3]);
            __half2 h2 = __floats2half2_rn(acc[i][4], acc[i][5]);
            __half2 h3 = __floats2half2_rn(acc[i][6], acc[i][7]);
            uint4 pk;
            pk.x = *(unsigned int*)&h0;
            pk.y = *(unsigned int*)&h1;
            pk.z = *(unsigned int*)&h2;
            pk.w = *(unsigned int*)&h3;
            *(uint4*)(C + (size_t)row * 128 + tx * 8) = pk;
        }
    }
}

// ---------------- CSR gather over F=128 (fp16 in), self-loop folded -------------
// acc[d] = sum_e coef_e * in[src_e] + dinv[d]^2 * in[d]     (fp32 accumulation)
// RELU_OUT: store relu(acc + b1) as fp16 into outh; else store acc fp32 into outf.
template<bool RELU_OUT>
__launch_bounds__(256)
__global__ void k_gather(const __half* __restrict__ in, const float* __restrict__ bias,
                         __half* __restrict__ outh, float* __restrict__ outf)
{
    int d = (blockIdx.x * 256 + threadIdx.x) >> 5;
    if (d >= NN) return;
    int lane = threadIdx.x & 31;
    int beg = g_off[d];
    int end = beg + g_degi[d];

    float4 acc = make_float4(0.f, 0.f, 0.f, 0.f);

#define LOAD4(sidx, f01, f23)                                               \
    {                                                                       \
        uint2 u = *(const uint2*)(in + (size_t)(sidx) * 128 + lane * 4);    \
        f01 = __half22float2(*(__half2*)&u.x);                              \
        f23 = __half22float2(*(__half2*)&u.y);                              \
    }

    int j = beg;
    for (; j + 3 < end; j += 4) {
        int   s0 = g_csr_src[j],      s1 = g_csr_src[j + 1];
        int   s2 = g_csr_src[j + 2],  s3 = g_csr_src[j + 3];
        float c0 = g_csr_coef[j],     c1 = g_csr_coef[j + 1];
        float c2 = g_csr_coef[j + 2], c3 = g_csr_coef[j + 3];
        float2 a01, a23, b01, b23, e01, e23, f01, f23;
        LOAD4(s0, a01, a23); LOAD4(s1, b01, b23);
        LOAD4(s2, e01, e23); LOAD4(s3, f01, f23);
        acc.x += c0 * a01.x + c1 * b01.x + c2 * e01.x + c3 * f01.x;
        acc.y += c0 * a01.y + c1 * b01.y + c2 * e01.y + c3 * f01.y;
        acc.z += c0 * a23.x + c1 * b23.x + c2 * e23.x + c3 * f23.x;
        acc.w += c0 * a23.y + c1 * b23.y + c2 * e23.y + c3 * f23.y;
    }
    for (; j < end; j++) {
        int   s0 = g_csr_src[j];
        float c0 = g_csr_coef[j];
        float2 a01, a23;
        LOAD4(s0, a01, a23);
        acc.x += c0 * a01.x; acc.y += c0 * a01.y;
        acc.z += c0 * a23.x; acc.w += c0 * a23.y;
    }

    // self loop
    {
        float dv = g_dinv[d];
        float c = dv * dv;
        float2 a01, a23;
        LOAD4(d, a01, a23);
        acc.x += c * a01.x; acc.y += c * a01.y;
        acc.z += c * a23.x; acc.w += c * a23.y;
    }
#undef LOAD4

    if (RELU_OUT) {
        float4 bb = *(const float4*)(bias + lane * 4);
        acc.x = fmaxf(acc.x + bb.x, 0.f);
        acc.y = fmaxf(acc.y + bb.y, 0.f);
        acc.z = fmaxf(acc.z + bb.z, 0.f);
        acc.w = fmaxf(acc.w + bb.w, 0.f);
        __half2 h0 = __floats2half2_rn(acc.x, acc.y);
        __half2 h1 = __floats2half2_rn(acc.z, acc.w);
        uint2 pk;
        pk.x = *(unsigned int*)&h0;
        pk.y = *(unsigned int*)&h1;
        *(uint2*)(outh + (size_t)d * 128 + lane * 4) = pk;
    } else {
        *(float4*)(outf + (size_t)d * 128 + lane * 4) = acc;
    }
}

// ---------------- pooling over h2 (F=128; batch sorted) ----------------
__global__ void k_pool()
{
    int f  = threadIdx.x;                        // 128 = F1
    int n0 = blockIdx.x * 64;
    int n1 = min(n0 + 64, NN);
    if (n0 >= NN) return;
    int curg = g_batch[n0];
    float acc = 0.0f;
    for (int n = n0; n < n1; n++) {
        int gg = g_batch[n];
        if (gg != curg) {
            atomicAdd(&g_psum[curg * F1 + f], acc);
            acc = 0.0f; curg = gg;
        }
        acc += g_h2[(size_t)n * F1 + f];
    }
    atomicAdd(&g_psum[curg * F1 + f], acc);
}

__global__ void k_cnts()
{
    int i = blockIdx.x * blockDim.x + threadIdx.x;
    if (i < NN) atomicAdd(&g_cnts[g_batch[i]], 1.0f);
}

// ---------------- pooled @ W2 + b2  -> g_pooled2 [NG, 256] ----------------
__global__ void k_w2pool(const float* __restrict__ W2, const float* __restrict__ b2)
{
    __shared__ float p[F1];
    int b = blockIdx.x, t = threadIdx.x;         // 256 threads
    float cnt = g_cnts[b];
    float inv = 1.0f / fmaxf(cnt, 1.0f);
    if (t < F1) p[t] = (cnt > 0.f) ? g_psum[b * F1 + t] * inv : 0.0f;
    __syncthreads();
    float a = (cnt > 0.f) ? b2[t] : 0.0f;
#pragma unroll 4
    for (int d = 0; d < F1; d++) a += p[d] * W2[d * F2 + t];
    g_pooled2[b * F2 + t] = a;
}

// ---------------- heads ----------------
__global__ void k_head(const float* __restrict__ Wg, const float* __restrict__ bg,
                       const float* __restrict__ Wf, const float* __restrict__ bf,
                       float* __restrict__ out)
{
    __shared__ float p[F2];
    int b = blockIdx.x, t = threadIdx.x;
    p[t] = g_pooled2[b * F2 + t];
    __syncthreads();
    if (t < NGRP) {
        float a = bg[t];
        for (int d = 0; d < F2; d++) a += p[d] * Wg[d * NGRP + t];
        out[b * NGRP + t] = a;
    } else if (t >= 64 && t < 64 + NGRP * NFAM) {
        int u = t - 64;
        int grp = u / NFAM, f = u - grp * NFAM;
        float a = bf[grp * NFAM + f];
        for (int d = 0; d < F2; d++) a += p[d] * Wf[(size_t)grp * F2 * NFAM + d * NFAM + f];
        out[NG * NGRP + (size_t)grp * NG * NFAM + b * NFAM + f] = a;
    }
}

// ---------------- launch ----------------
extern "C" void kernel_launch(void* const* d_in, const int* in_sizes, int n_in,
                              void* d_out, int out_size)
{
    const float* x    = (const float*)d_in[0];
    const void*  eidx = d_in[1];
    const void*  batc = d_in[2];
    const float* W1   = (const float*)d_in[3];
    const float* b1   = (const float*)d_in[4];
    const float* W2   = (const float*)d_in[5];
    const float* b2   = (const float*)d_in[6];
    const float* Wg   = (const float*)d_in[7];
    const float* bg   = (const float*)d_in[8];
    const float* Wf   = (const float*)d_in[9];
    const float* bf   = (const float*)d_in[10];
    float* out = (float*)d_out;

    __half *xw1h, *r1h;
    float *h2;
    int *eidx32, *batch32;
    cudaGetSymbolAddress((void**)&xw1h, g_xw1h);
    cudaGetSymbolAddress((void**)&r1h,  g_r1h);
    cudaGetSymbolAddress((void**)&h2,   g_h2);
    cudaGetSymbolAddress((void**)&eidx32,  g_eidx);
    cudaGetSymbolAddress((void**)&batch32, g_batch);

    // normalize index dtypes
    k_detect<<<1, 1>>>((const unsigned int*)eidx);
    k_convert<<<(2 * NE + 255) / 256, 256>>>((const int*)eidx, eidx32, 2 * NE);
    k_convert<<<(NN + 255) / 256, 256>>>((const int*)batc, batch32, NN);

    // GEMM1: xw1 = x @ W1 (fp16 out)
    k_gemm1<<<(NN + 127) / 128, 256>>>(x, W1, xw1h, NN);

    // degree + dinv
    k_init<<<(INIT_N + 255) / 256, 256>>>();
    k_deg_count<<<(NE + 255) / 256, 256>>>();
    k_dinv<<<(NN + 255) / 256, 256>>>();

    // CSR build (dst-sorted)
    k_scan_local<<<NBLK, SB>>>();
    k_scan_bsum<<<1, 256>>>();
    k_scan_add<<<NBLK, SB>>>();
    k_fill<<<(NE + 255) / 256, 256>>>();

    // layer 1 aggregate + relu:  r1 = relu(A_hat*xw1 + b1)  (fp16 out)
    k_gather<true><<<(NN * 32 + 255) / 256, 256>>>(xw1h, b1, r1h, nullptr);

    // layer 2 aggregate: h2 = A_hat * r1  (fp32 out)
    k_gather<false><<<(NN * 32 + 255) / 256, 256>>>(r1h, nullptr, nullptr, h2);

    // pool h2 per graph, tiny GEMM, heads
    k_pool<<<(NN + 63) / 64, 128>>>();
    k_cnts<<<(NN + 255) / 256, 256>>>();
    k_w2pool<<<NG, 256>>>(W2, b2);
    k_head<<<NG, 256>>>(Wg, bg, Wf, bf, out);
}

// round 8
// speedup vs baseline: 7.2467x; 1.2332x over previous
#include <cuda_runtime.h>
#include <cuda_bf16.h>
#include <cuda_fp16.h>
#include <math.h>

// ---------------- problem constants ----------------
#define NN 100000          // nodes
#define NE 1600000         // edges
#define NG 512             // graphs
#define F1 128             // IN_F == H1
#define F2 256             // H2
#define NGRP 16
#define NFAM 10

#define SB 512
#define NBLK ((NN + SB - 1) / SB)   // 196 scan blocks
#define INIT_N (NG * F2)

// HMMA GEMM1 geometry
#define ASTRIDE 136                     // 128 + 8 halves pad
#define HSMEM_BYTES (2 * 128 * ASTRIDE * 2)   // A + B panels, fp16

// ---------------- device scratch (no allocations allowed) ----------------
__device__ __half g_xw1h[ (size_t)NN * F1 ];  // x @ W1          (fp16 storage)
__device__ __half g_r1h [ (size_t)NN * F1 ];  // relu(A*xw1+b1)  (fp16 storage)
__device__ float  g_h2  [ (size_t)NN * F1 ];  // A_hat * r1      (fp32)
__device__ float  g_psum[ NG * F1 ];
__device__ float  g_pooled2[ NG * F2 ];
__device__ float  g_dinv[ NN ];
__device__ float  g_cnts[ NG ];
__device__ int    g_eidx[ 2 * NE ];
__device__ int    g_batch[ NN ];
__device__ int    g_is64;
__device__ int    g_degi  [ NN ];
__device__ int    g_off   [ NN ];
__device__ int    g_cursor[ NN ];
__device__ int    g_bsum  [ 256 ];
__device__ int    g_csr_src [ NE ];
__device__ float  g_csr_coef[ NE ];

// ---------------- dtype detection + index normalization ----------------
__global__ void k_detect(const unsigned int* __restrict__ e) {
    int is64 = 1;
    for (int i = 0; i < 64; i++)
        if (e[2 * i + 1] != 0u) { is64 = 0; break; }
    g_is64 = is64;
}

__global__ void k_convert(const int* __restrict__ in, int* __restrict__ out, int n) {
    int i = blockIdx.x * blockDim.x + threadIdx.x;
    if (i >= n) return;
    out[i] = g_is64 ? in[2 * i] : in[i];
}

// ---------------- init / degree ----------------
__global__ void k_init() {
    int i = blockIdx.x * blockDim.x + threadIdx.x;
    if (i < NN) g_degi[i] = 0;
    if (i < NG * F1) g_psum[i] = 0.0f;
    if (i < NG) g_cnts[i] = 0.0f;
}

__global__ void k_deg_count() {
    int e = blockIdx.x * blockDim.x + threadIdx.x;
    if (e >= NE) return;
    atomicAdd(&g_degi[g_eidx[NE + e]], 1);
}

__global__ void k_dinv() {
    int i = blockIdx.x * blockDim.x + threadIdx.x;
    if (i < NN) g_dinv[i] = rsqrtf((float)(g_degi[i] + 1));
}

// ---------------- exclusive scan over g_degi -> g_off ----------------
__global__ void k_scan_local() {
    __shared__ int sh[SB];
    int i = blockIdx.x * SB + threadIdx.x;
    int v = (i < NN) ? g_degi[i] : 0;
    sh[threadIdx.x] = v;
    __syncthreads();
    for (int off = 1; off < SB; off <<= 1) {
        int t = (threadIdx.x >= off) ? sh[threadIdx.x - off] : 0;
        __syncthreads();
        sh[threadIdx.x] += t;
        __syncthreads();
    }
    if (i < NN) g_off[i] = sh[threadIdx.x] - v;
    if (threadIdx.x == SB - 1) g_bsum[blockIdx.x] = sh[SB - 1];
}

__global__ void k_scan_bsum() {
    __shared__ int sh[256];
    int t = threadIdx.x;
    int v = (t < NBLK) ? g_bsum[t] : 0;
    sh[t] = v;
    __syncthreads();
    for (int off = 1; off < 256; off <<= 1) {
        int u = (t >= off) ? sh[t - off] : 0;
        __syncthreads();
        sh[t] += u;
        __syncthreads();
    }
    if (t < NBLK) g_bsum[t] = sh[t] - v;
}

__global__ void k_scan_add() {
    int i = blockIdx.x * SB + threadIdx.x;
    if (i < NN) {
        int o = g_off[i] + g_bsum[blockIdx.x];
        g_off[i] = o;
        g_cursor[i] = o;
    }
}

// ---------------- CSR fill ----------------
__global__ void k_fill() {
    int e = blockIdx.x * blockDim.x + threadIdx.x;
    if (e >= NE) return;
    int s = g_eidx[e];
    int d = g_eidx[NE + e];
    int slot = atomicAdd(&g_cursor[d], 1);
    g_csr_src[slot] = s;
    g_csr_coef[slot] = g_dinv[s] * g_dinv[d];
}

// ---------------- HMMA GEMM1: C[M,128] = A[M,128] * B[128,128], fp16 io ---------
// 256 threads = 8 warps (4 m-groups x 2 n-groups); warp tile 32x64.
// Whole K=128 panel staged once in smem (fp16, pad 8). mma.sync m16n8k16.
__launch_bounds__(256)
__global__ void k_hgemm(const float* __restrict__ A, const float* __restrict__ B,
                        __half* __restrict__ C, int M)
{
    extern __shared__ __half smem[];
    __half* As  = smem;                 // [128][ASTRIDE]
    __half* Bsm = smem + 128 * ASTRIDE; // [128][ASTRIDE]

    const int tid  = threadIdx.x;
    const int lane = tid & 31;
    const int wid  = tid >> 5;
    const int wm   = wid >> 1;          // 0..3
    const int wn   = wid & 1;           // 0..1
    const int row0 = blockIdx.x * 128;

    // stage A (x rows, fp32 -> fp16) and B (W1, fp32 -> fp16)
#pragma unroll
    for (int i = 0; i < 16; i++) {
        int idx = tid + i * 256;        // 0..4095
        int row = idx >> 5;
        int c4  = idx & 31;
        float4 v = make_float4(0.f, 0.f, 0.f, 0.f);
        if (row0 + row < M)
            v = *(const float4*)(A + (size_t)(row0 + row) * 128 + c4 * 4);
        __half2 h01 = __floats2half2_rn(v.x, v.y);
        __half2 h23 = __floats2half2_rn(v.z, v.w);
        uint2 pk;
        pk.x = *(unsigned int*)&h01;
        pk.y = *(unsigned int*)&h23;
        *(uint2*)(As + row * ASTRIDE + c4 * 4) = pk;

        float4 w = *(const float4*)(B + (size_t)row * 128 + c4 * 4);
        __half2 w01 = __floats2half2_rn(w.x, w.y);
        __half2 w23 = __floats2half2_rn(w.z, w.w);
        uint2 pw;
        pw.x = *(unsigned int*)&w01;
        pw.y = *(unsigned int*)&w23;
        *(uint2*)(Bsm + row * ASTRIDE + c4 * 4) = pw;
    }
    __syncthreads();

    float acc[2][8][4];
#pragma unroll
    for (int mt = 0; mt < 2; mt++)
#pragma unroll
        for (int nt = 0; nt < 8; nt++)
#pragma unroll
            for (int r = 0; r < 4; r++) acc[mt][nt][r] = 0.0f;

#pragma unroll
    for (int kc = 0; kc < 8; kc++) {
        int k0 = kc * 16;
        // A fragments (2 m-tiles of 16)
        unsigned int a[2][4];
#pragma unroll
        for (int mt = 0; mt < 2; mt++) {
            int r = wm * 32 + mt * 16 + (lane & 15);
            int c = k0 + (lane >> 4) * 8;
            unsigned int addr = (unsigned int)__cvta_generic_to_shared(As + r * ASTRIDE + c);
            asm volatile("ldmatrix.sync.aligned.m8n8.x4.shared.b16 {%0,%1,%2,%3}, [%4];"
                         : "=r"(a[mt][0]), "=r"(a[mt][1]), "=r"(a[mt][2]), "=r"(a[mt][3])
                         : "r"(addr));
        }
        // B fragments (8 n-tiles of 8, fetched as 4 x (16x16 trans))
        unsigned int b[8][2];
#pragma unroll
        for (int p = 0; p < 4; p++) {
            int r = k0 + (lane & 15);
            int c = wn * 64 + p * 16 + (lane >> 4) * 8;
            unsigned int addr = (unsigned int)__cvta_generic_to_shared(Bsm + r * ASTRIDE + c);
            unsigned int r0, r1, r2, r3;
            asm volatile("ldmatrix.sync.aligned.m8n8.x4.trans.shared.b16 {%0,%1,%2,%3}, [%4];"
                         : "=r"(r0), "=r"(r1), "=r"(r2), "=r"(r3)
                         : "r"(addr));
            b[p * 2][0] = r0; b[p * 2][1] = r1;
            b[p * 2 + 1][0] = r2; b[p * 2 + 1][1] = r3;
        }
#pragma unroll
        for (int mt = 0; mt < 2; mt++)
#pragma unroll
            for (int nt = 0; nt < 8; nt++)
                asm volatile("mma.sync.aligned.m16n8k16.row.col.f32.f16.f16.f32 "
                             "{%0,%1,%2,%3}, {%4,%5,%6,%7}, {%8,%9}, {%0,%1,%2,%3};"
                             : "+f"(acc[mt][nt][0]), "+f"(acc[mt][nt][1]),
                               "+f"(acc[mt][nt][2]), "+f"(acc[mt][nt][3])
                             : "r"(a[mt][0]), "r"(a[mt][1]), "r"(a[mt][2]), "r"(a[mt][3]),
                               "r"(b[nt][0]), "r"(b[nt][1]));
    }

    // epilogue: fp32 acc -> fp16 direct stores
    const int g  = lane >> 2;           // 0..7
    const int t4 = lane & 3;            // 0..3
#pragma unroll
    for (int mt = 0; mt < 2; mt++) {
#pragma unroll
        for (int nt = 0; nt < 8; nt++) {
            int row = row0 + wm * 32 + mt * 16 + g;
            int col = wn * 64 + nt * 8 + t4 * 2;
            if (row < M) {
                __half2 h = __floats2half2_rn(acc[mt][nt][0], acc[mt][nt][1]);
                *(__half2*)(C + (size_t)row * 128 + col) = h;
            }
            if (row + 8 < M) {
                __half2 h = __floats2half2_rn(acc[mt][nt][2], acc[mt][nt][3]);
                *(__half2*)(C + (size_t)(row + 8) * 128 + col) = h;
            }
        }
    }
}

// ---------------- CSR gather over F=128 (fp16 in), self-loop folded -------------
template<bool RELU_OUT>
__launch_bounds__(256)
__global__ void k_gather(const __half* __restrict__ in, const float* __restrict__ bias,
                         __half* __restrict__ outh, float* __restrict__ outf)
{
    int d = (blockIdx.x * 256 + threadIdx.x) >> 5;
    if (d >= NN) return;
    int lane = threadIdx.x & 31;
    int beg = g_off[d];
    int end = beg + g_degi[d];

    float4 acc = make_float4(0.f, 0.f, 0.f, 0.f);

#define LOAD4(sidx, f01, f23)                                               \
    {                                                                       \
        uint2 u = *(const uint2*)(in + (size_t)(sidx) * 128 + lane * 4);    \
        f01 = __half22float2(*(__half2*)&u.x);                              \
        f23 = __half22float2(*(__half2*)&u.y);                              \
    }

    int j = beg;
    for (; j + 3 < end; j += 4) {
        int   s0 = g_csr_src[j],      s1 = g_csr_src[j + 1];
        int   s2 = g_csr_src[j + 2],  s3 = g_csr_src[j + 3];
        float c0 = g_csr_coef[j],     c1 = g_csr_coef[j + 1];
        float c2 = g_csr_coef[j + 2], c3 = g_csr_coef[j + 3];
        float2 a01, a23, b01, b23, e01, e23, f01, f23;
        LOAD4(s0, a01, a23); LOAD4(s1, b01, b23);
        LOAD4(s2, e01, e23); LOAD4(s3, f01, f23);
        acc.x += c0 * a01.x + c1 * b01.x + c2 * e01.x + c3 * f01.x;
        acc.y += c0 * a01.y + c1 * b01.y + c2 * e01.y + c3 * f01.y;
        acc.z += c0 * a23.x + c1 * b23.x + c2 * e23.x + c3 * f23.x;
        acc.w += c0 * a23.y + c1 * b23.y + c2 * e23.y + c3 * f23.y;
    }
    for (; j < end; j++) {
        int   s0 = g_csr_src[j];
        float c0 = g_csr_coef[j];
        float2 a01, a23;
        LOAD4(s0, a01, a23);
        acc.x += c0 * a01.x; acc.y += c0 * a01.y;
        acc.z += c0 * a23.x; acc.w += c0 * a23.y;
    }

    // self loop
    {
        float dv = g_dinv[d];
        float c = dv * dv;
        float2 a01, a23;
        LOAD4(d, a01, a23);
        acc.x += c * a01.x; acc.y += c * a01.y;
        acc.z += c * a23.x; acc.w += c * a23.y;
    }
#undef LOAD4

    if (RELU_OUT) {
        float4 bb = *(const float4*)(bias + lane * 4);
        acc.x = fmaxf(acc.x + bb.x, 0.f);
        acc.y = fmaxf(acc.y + bb.y, 0.f);
        acc.z = fmaxf(acc.z + bb.z, 0.f);
        acc.w = fmaxf(acc.w + bb.w, 0.f);
        __half2 h0 = __floats2half2_rn(acc.x, acc.y);
        __half2 h1 = __floats2half2_rn(acc.z, acc.w);
        uint2 pk;
        pk.x = *(unsigned int*)&h0;
        pk.y = *(unsigned int*)&h1;
        *(uint2*)(outh + (size_t)d * 128 + lane * 4) = pk;
    } else {
        *(float4*)(outf + (size_t)d * 128 + lane * 4) = acc;
    }
}

// ---------------- pooling over h2 (F=128; batch sorted) ----------------
__global__ void k_pool()
{
    int f  = threadIdx.x;
    int n0 = blockIdx.x * 64;
    int n1 = min(n0 + 64, NN);
    if (n0 >= NN) return;
    int curg = g_batch[n0];
    float acc = 0.0f;
    for (int n = n0; n < n1; n++) {
        int gg = g_batch[n];
        if (gg != curg) {
            atomicAdd(&g_psum[curg * F1 + f], acc);
            acc = 0.0f; curg = gg;
        }
        acc += g_h2[(size_t)n * F1 + f];
    }
    atomicAdd(&g_psum[curg * F1 + f], acc);
}

__global__ void k_cnts()
{
    int i = blockIdx.x * blockDim.x + threadIdx.x;
    if (i < NN) atomicAdd(&g_cnts[g_batch[i]], 1.0f);
}

// ---------------- pooled @ W2 + b2 ----------------
__global__ void k_w2pool(const float* __restrict__ W2, const float* __restrict__ b2)
{
    __shared__ float p[F1];
    int b = blockIdx.x, t = threadIdx.x;
    float cnt = g_cnts[b];
    float inv = 1.0f / fmaxf(cnt, 1.0f);
    if (t < F1) p[t] = (cnt > 0.f) ? g_psum[b * F1 + t] * inv : 0.0f;
    __syncthreads();
    float a = (cnt > 0.f) ? b2[t] : 0.0f;
#pragma unroll 4
    for (int d = 0; d < F1; d++) a += p[d] * W2[d * F2 + t];
    g_pooled2[b * F2 + t] = a;
}

// ---------------- heads ----------------
__global__ void k_head(const float* __restrict__ Wg, const float* __restrict__ bg,
                       const float* __restrict__ Wf, const float* __restrict__ bf,
                       float* __restrict__ out)
{
    __shared__ float p[F2];
    int b = blockIdx.x, t = threadIdx.x;
    p[t] = g_pooled2[b * F2 + t];
    __syncthreads();
    if (t < NGRP) {
        float a = bg[t];
        for (int d = 0; d < F2; d++) a += p[d] * Wg[d * NGRP + t];
        out[b * NGRP + t] = a;
    } else if (t >= 64 && t < 64 + NGRP * NFAM) {
        int u = t - 64;
        int grp = u / NFAM, f = u - grp * NFAM;
        float a = bf[grp * NFAM + f];
        for (int d = 0; d < F2; d++) a += p[d] * Wf[(size_t)grp * F2 * NFAM + d * NFAM + f];
        out[NG * NGRP + (size_t)grp * NG * NFAM + b * NFAM + f] = a;
    }
}

// ---------------- launch ----------------
extern "C" void kernel_launch(void* const* d_in, const int* in_sizes, int n_in,
                              void* d_out, int out_size)
{
    const float* x    = (const float*)d_in[0];
    const void*  eidx = d_in[1];
    const void*  batc = d_in[2];
    const float* W1   = (const float*)d_in[3];
    const float* b1   = (const float*)d_in[4];
    const float* W2   = (const float*)d_in[5];
    const float* b2   = (const float*)d_in[6];
    const float* Wg   = (const float*)d_in[7];
    const float* bg   = (const float*)d_in[8];
    const float* Wf   = (const float*)d_in[9];
    const float* bf   = (const float*)d_in[10];
    float* out = (float*)d_out;

    __half *xw1h, *r1h;
    float *h2;
    int *eidx32, *batch32;
    cudaGetSymbolAddress((void**)&xw1h, g_xw1h);
    cudaGetSymbolAddress((void**)&r1h,  g_r1h);
    cudaGetSymbolAddress((void**)&h2,   g_h2);
    cudaGetSymbolAddress((void**)&eidx32,  g_eidx);
    cudaGetSymbolAddress((void**)&batch32, g_batch);

    // opt-in to >48KB dynamic smem for the HMMA GEMM (idempotent, capture-safe)
    cudaFuncSetAttribute(k_hgemm, cudaFuncAttributeMaxDynamicSharedMemorySize, HSMEM_BYTES);

    // normalize index dtypes
    k_detect<<<1, 1>>>((const unsigned int*)eidx);
    k_convert<<<(2 * NE + 255) / 256, 256>>>((const int*)eidx, eidx32, 2 * NE);
    k_convert<<<(NN + 255) / 256, 256>>>((const int*)batc, batch32, NN);

    // GEMM1 (tensor cores): xw1 = x @ W1 (fp16 out)  -- profiled slot
    k_hgemm<<<(NN + 127) / 128, 256, HSMEM_BYTES>>>(x, W1, xw1h, NN);

    // degree + dinv
    k_init<<<(INIT_N + 255) / 256, 256>>>();
    k_deg_count<<<(NE + 255) / 256, 256>>>();
    k_dinv<<<(NN + 255) / 256, 256>>>();

    // CSR build (dst-sorted)
    k_scan_local<<<NBLK, SB>>>();
    k_scan_bsum<<<1, 256>>>();
    k_scan_add<<<NBLK, SB>>>();
    k_fill<<<(NE + 255) / 256, 256>>>();

    // layer 1 aggregate + relu:  r1 = relu(A_hat*xw1 + b1)  (fp16 out)
    k_gather<true><<<(NN * 32 + 255) / 256, 256>>>(xw1h, b1, r1h, nullptr);

    // layer 2 aggregate: h2 = A_hat * r1  (fp32 out)
    k_gather<false><<<(NN * 32 + 255) / 256, 256>>>(r1h, nullptr, nullptr, h2);

    // pool h2 per graph, tiny GEMM, heads
    k_pool<<<(NN + 63) / 64, 128>>>();
    k_cnts<<<(NN + 255) / 256, 256>>>();
    k_w2pool<<<NG, 256>>>(W2, b2);
    k_head<<<NG, 256>>>(Wg, bg, Wf, bf, out);
}

// round 9
// speedup vs baseline: 8.9693x; 1.2377x over previous
#include <cuda_runtime.h>
#include <cuda_bf16.h>
#include <cuda_fp16.h>
#include <math.h>

// ---------------- problem constants ----------------
#define NN 100000          // nodes
#define NE 1600000         // edges
#define NG 512             // graphs
#define F1 128             // IN_F == H1
#define F2 256             // H2
#define NGRP 16
#define NFAM 10

#define SB 512
#define NBLK ((NN + SB - 1) / SB)   // 196 scan blocks
#define INIT_N (NG * F2)

// HMMA GEMM1 geometry
#define ASTRIDE 136                     // 128 + 8 halves pad
#define HSMEM_BYTES (2 * 128 * ASTRIDE * 2)   // A + B panels, fp16

// ---------------- device scratch (no allocations allowed) ----------------
__device__ __half g_xw1h[ (size_t)NN * F1 ];  // x @ W1          (fp16)
__device__ __half g_r1h [ (size_t)NN * F1 ];  // relu(A*xw1+b1)  (fp16)
__device__ __half g_h2h [ (size_t)NN * F1 ];  // A_hat * r1      (fp16)
__device__ float  g_psum[ NG * F1 ];
__device__ float  g_dinv[ NN ];
__device__ float  g_cnts[ NG ];
__device__ int2   g_e2  [ NE ];               // (src, dst) interleaved
__device__ int    g_batch[ NN ];
__device__ int    g_is64;
__device__ int    g_degi  [ NN ];
__device__ int    g_off   [ NN ];
__device__ int    g_cursor[ NN ];
__device__ int    g_bsum  [ 256 ];
__device__ int2   g_csr   [ NE ];             // (src, coef bits) interleaved

// ---------------- dtype detection ----------------
__global__ void k_detect(const unsigned int* __restrict__ e) {
    int is64 = 1;
    for (int i = 0; i < 64; i++)
        if (e[2 * i + 1] != 0u) { is64 = 0; break; }
    g_is64 = is64;
}

// ---------------- init ----------------
__global__ void k_init() {
    int i = blockIdx.x * blockDim.x + threadIdx.x;
    if (i < NN) g_degi[i] = 0;
    if (i < NG * F1) g_psum[i] = 0.0f;
    if (i < NG) g_cnts[i] = 0.0f;
}

// ---------------- edge convert + degree count (fused, one pass) ----------------
__global__ void k_conv_edges(const int* __restrict__ in) {
    int e = blockIdx.x * blockDim.x + threadIdx.x;
    if (e >= NE) return;
    int s, d;
    if (g_is64) { s = in[2 * e]; d = in[2 * (NE + e)]; }
    else        { s = in[e];     d = in[NE + e]; }
    g_e2[e] = make_int2(s, d);
    atomicAdd(&g_degi[d], 1);
}

__global__ void k_conv_batch(const int* __restrict__ in) {
    int i = blockIdx.x * blockDim.x + threadIdx.x;
    if (i >= NN) return;
    g_batch[i] = g_is64 ? in[2 * i] : in[i];
}

// ---------------- exclusive scan over g_degi -> g_off (+ dinv fold) ------------
__global__ void k_scan_local() {
    __shared__ int sh[SB];
    int i = blockIdx.x * SB + threadIdx.x;
    int v = (i < NN) ? g_degi[i] : 0;
    sh[threadIdx.x] = v;
    __syncthreads();
    for (int off = 1; off < SB; off <<= 1) {
        int t = (threadIdx.x >= off) ? sh[threadIdx.x - off] : 0;
        __syncthreads();
        sh[threadIdx.x] += t;
        __syncthreads();
    }
    if (i < NN) g_off[i] = sh[threadIdx.x] - v;
    if (threadIdx.x == SB - 1) g_bsum[blockIdx.x] = sh[SB - 1];
}

__global__ void k_scan_bsum() {
    __shared__ int sh[256];
    int t = threadIdx.x;
    int v = (t < NBLK) ? g_bsum[t] : 0;
    sh[t] = v;
    __syncthreads();
    for (int off = 1; off < 256; off <<= 1) {
        int u = (t >= off) ? sh[t - off] : 0;
        __syncthreads();
        sh[t] += u;
        __syncthreads();
    }
    if (t < NBLK) g_bsum[t] = sh[t] - v;
}

__global__ void k_scan_add() {
    int i = blockIdx.x * SB + threadIdx.x;
    if (i < NN) {
        int o = g_off[i] + g_bsum[blockIdx.x];
        g_off[i] = o;
        g_cursor[i] = o;
        g_dinv[i] = rsqrtf((float)(g_degi[i] + 1));
    }
}

// ---------------- CSR fill: per-dst segments of (src, coef) ----------------
__global__ void k_fill() {
    int e = blockIdx.x * blockDim.x + threadIdx.x;
    if (e >= NE) return;
    int2 sd = g_e2[e];
    float coef = g_dinv[sd.x] * g_dinv[sd.y];
    int slot = atomicAdd(&g_cursor[sd.y], 1);
    g_csr[slot] = make_int2(sd.x, __float_as_int(coef));
}

// ---------------- HMMA GEMM1: C[M,128] = A[M,128] * B[128,128], fp16 out --------
__launch_bounds__(256)
__global__ void k_hgemm(const float* __restrict__ A, const float* __restrict__ B,
                        __half* __restrict__ C, int M)
{
    extern __shared__ __half smem[];
    __half* As  = smem;                 // [128][ASTRIDE]
    __half* Bsm = smem + 128 * ASTRIDE; // [128][ASTRIDE]

    const int tid  = threadIdx.x;
    const int lane = tid & 31;
    const int wid  = tid >> 5;
    const int wm   = wid >> 1;
    const int wn   = wid & 1;
    const int row0 = blockIdx.x * 128;

#pragma unroll
    for (int i = 0; i < 16; i++) {
        int idx = tid + i * 256;
        int row = idx >> 5;
        int c4  = idx & 31;
        float4 v = make_float4(0.f, 0.f, 0.f, 0.f);
        if (row0 + row < M)
            v = *(const float4*)(A + (size_t)(row0 + row) * 128 + c4 * 4);
        __half2 h01 = __floats2half2_rn(v.x, v.y);
        __half2 h23 = __floats2half2_rn(v.z, v.w);
        uint2 pk;
        pk.x = *(unsigned int*)&h01;
        pk.y = *(unsigned int*)&h23;
        *(uint2*)(As + row * ASTRIDE + c4 * 4) = pk;

        float4 w = *(const float4*)(B + (size_t)row * 128 + c4 * 4);
        __half2 w01 = __floats2half2_rn(w.x, w.y);
        __half2 w23 = __floats2half2_rn(w.z, w.w);
        uint2 pw;
        pw.x = *(unsigned int*)&w01;
        pw.y = *(unsigned int*)&w23;
        *(uint2*)(Bsm + row * ASTRIDE + c4 * 4) = pw;
    }
    __syncthreads();

    float acc[2][8][4];
#pragma unroll
    for (int mt = 0; mt < 2; mt++)
#pragma unroll
        for (int nt = 0; nt < 8; nt++)
#pragma unroll
            for (int r = 0; r < 4; r++) acc[mt][nt][r] = 0.0f;

#pragma unroll
    for (int kc = 0; kc < 8; kc++) {
        int k0 = kc * 16;
        unsigned int a[2][4];
#pragma unroll
        for (int mt = 0; mt < 2; mt++) {
            int r = wm * 32 + mt * 16 + (lane & 15);
            int c = k0 + (lane >> 4) * 8;
            unsigned int addr = (unsigned int)__cvta_generic_to_shared(As + r * ASTRIDE + c);
            asm volatile("ldmatrix.sync.aligned.m8n8.x4.shared.b16 {%0,%1,%2,%3}, [%4];"
                         : "=r"(a[mt][0]), "=r"(a[mt][1]), "=r"(a[mt][2]), "=r"(a[mt][3])
                         : "r"(addr));
        }
        unsigned int b[8][2];
#pragma unroll
        for (int p = 0; p < 4; p++) {
            int r = k0 + (lane & 15);
            int c = wn * 64 + p * 16 + (lane >> 4) * 8;
            unsigned int addr = (unsigned int)__cvta_generic_to_shared(Bsm + r * ASTRIDE + c);
            unsigned int r0, r1, r2, r3;
            asm volatile("ldmatrix.sync.aligned.m8n8.x4.trans.shared.b16 {%0,%1,%2,%3}, [%4];"
                         : "=r"(r0), "=r"(r1), "=r"(r2), "=r"(r3)
                         : "r"(addr));
            b[p * 2][0] = r0; b[p * 2][1] = r1;
            b[p * 2 + 1][0] = r2; b[p * 2 + 1][1] = r3;
        }
#pragma unroll
        for (int mt = 0; mt < 2; mt++)
#pragma unroll
            for (int nt = 0; nt < 8; nt++)
                asm volatile("mma.sync.aligned.m16n8k16.row.col.f32.f16.f16.f32 "
                             "{%0,%1,%2,%3}, {%4,%5,%6,%7}, {%8,%9}, {%0,%1,%2,%3};"
                             : "+f"(acc[mt][nt][0]), "+f"(acc[mt][nt][1]),
                               "+f"(acc[mt][nt][2]), "+f"(acc[mt][nt][3])
                             : "r"(a[mt][0]), "r"(a[mt][1]), "r"(a[mt][2]), "r"(a[mt][3]),
                               "r"(b[nt][0]), "r"(b[nt][1]));
    }

    const int g  = lane >> 2;
    const int t4 = lane & 3;
#pragma unroll
    for (int mt = 0; mt < 2; mt++) {
#pragma unroll
        for (int nt = 0; nt < 8; nt++) {
            int row = row0 + wm * 32 + mt * 16 + g;
            int col = wn * 64 + nt * 8 + t4 * 2;
            if (row < M) {
                __half2 h = __floats2half2_rn(acc[mt][nt][0], acc[mt][nt][1]);
                *(__half2*)(C + (size_t)row * 128 + col) = h;
            }
            if (row + 8 < M) {
                __half2 h = __floats2half2_rn(acc[mt][nt][2], acc[mt][nt][3]);
                *(__half2*)(C + (size_t)(row + 8) * 128 + col) = h;
            }
        }
    }
}

// ---------------- CSR gather over F=128 (fp16 in/out), self-loop folded ---------
// acc[d] = sum_e coef_e * in[src_e] + dinv[d]^2 * in[d]     (fp32 accumulation)
// RELU_OUT: store relu(acc + b1) fp16; else store acc fp16.
template<bool RELU_OUT>
__launch_bounds__(256)
__global__ void k_gather(const __half* __restrict__ in, const float* __restrict__ bias,
                         __half* __restrict__ outh)
{
    int d = (blockIdx.x * 256 + threadIdx.x) >> 5;
    if (d >= NN) return;
    int lane = threadIdx.x & 31;
    int beg = g_off[d];
    int end = beg + g_degi[d];

    float4 acc = make_float4(0.f, 0.f, 0.f, 0.f);

#define LOAD4(sidx, f01, f23)                                               \
    {                                                                       \
        uint2 u = *(const uint2*)(in + (size_t)(sidx) * 128 + lane * 4);    \
        f01 = __half22float2(*(__half2*)&u.x);                              \
        f23 = __half22float2(*(__half2*)&u.y);                              \
    }

    int j = beg;
    for (; j + 3 < end; j += 4) {
        int2 e0 = g_csr[j],     e1 = g_csr[j + 1];
        int2 e2 = g_csr[j + 2], e3 = g_csr[j + 3];
        float c0 = __int_as_float(e0.y), c1 = __int_as_float(e1.y);
        float c2 = __int_as_float(e2.y), c3 = __int_as_float(e3.y);
        float2 a01, a23, b01, b23, e01, e23, f01, f23;
        LOAD4(e0.x, a01, a23); LOAD4(e1.x, b01, b23);
        LOAD4(e2.x, e01, e23); LOAD4(e3.x, f01, f23);
        acc.x += c0 * a01.x + c1 * b01.x + c2 * e01.x + c3 * f01.x;
        acc.y += c0 * a01.y + c1 * b01.y + c2 * e01.y + c3 * f01.y;
        acc.z += c0 * a23.x + c1 * b23.x + c2 * e23.x + c3 * f23.x;
        acc.w += c0 * a23.y + c1 * b23.y + c2 * e23.y + c3 * f23.y;
    }
    for (; j < end; j++) {
        int2 e0 = g_csr[j];
        float c0 = __int_as_float(e0.y);
        float2 a01, a23;
        LOAD4(e0.x, a01, a23);
        acc.x += c0 * a01.x; acc.y += c0 * a01.y;
        acc.z += c0 * a23.x; acc.w += c0 * a23.y;
    }

    // self loop
    {
        float dv = g_dinv[d];
        float c = dv * dv;
        float2 a01, a23;
        LOAD4(d, a01, a23);
        acc.x += c * a01.x; acc.y += c * a01.y;
        acc.z += c * a23.x; acc.w += c * a23.y;
    }
#undef LOAD4

    if (RELU_OUT) {
        float4 bb = *(const float4*)(bias + lane * 4);
        acc.x = fmaxf(acc.x + bb.x, 0.f);
        acc.y = fmaxf(acc.y + bb.y, 0.f);
        acc.z = fmaxf(acc.z + bb.z, 0.f);
        acc.w = fmaxf(acc.w + bb.w, 0.f);
    }
    __half2 h0 = __floats2half2_rn(acc.x, acc.y);
    __half2 h1 = __floats2half2_rn(acc.z, acc.w);
    uint2 pk;
    pk.x = *(unsigned int*)&h0;
    pk.y = *(unsigned int*)&h1;
    *(uint2*)(outh + (size_t)d * 128 + lane * 4) = pk;
}

// ---------------- pooling over h2 fp16 (batch sorted) + counts ----------------
__global__ void k_pool()
{
    int f  = threadIdx.x;                 // 128 = F1
    int n0 = blockIdx.x * 64;
    int n1 = min(n0 + 64, NN);
    if (n0 >= NN) return;
    int curg = g_batch[n0];
    float acc = 0.0f;
    int   cnt = 0;
    for (int n = n0; n < n1; n++) {
        int gg = g_batch[n];
        if (gg != curg) {
            atomicAdd(&g_psum[curg * F1 + f], acc);
            if (f == 0) atomicAdd(&g_cnts[curg], (float)cnt);
            acc = 0.0f; cnt = 0; curg = gg;
        }
        acc += __half2float(g_h2h[(size_t)n * F1 + f]);
        cnt++;
    }
    atomicAdd(&g_psum[curg * F1 + f], acc);
    if (f == 0) atomicAdd(&g_cnts[curg], (float)cnt);
}

// ---------------- fused: pooled@W2+b2 then heads ----------------
__global__ void k_w2head(const float* __restrict__ W2, const float* __restrict__ b2,
                         const float* __restrict__ Wg, const float* __restrict__ bg,
                         const float* __restrict__ Wf, const float* __restrict__ bf,
                         float* __restrict__ out)
{
    __shared__ float p[F1];
    __shared__ float p2[F2];
    int b = blockIdx.x, t = threadIdx.x;          // 256 threads
    float inv = 1.0f / fmaxf(g_cnts[b], 1.0f);
    if (t < F1) p[t] = g_psum[b * F1 + t] * inv;
    __syncthreads();
    float a = b2[t];
#pragma unroll 4
    for (int d = 0; d < F1; d++) a += p[d] * W2[d * F2 + t];
    p2[t] = a;
    __syncthreads();
    if (t < NGRP) {
        float s = bg[t];
        for (int d = 0; d < F2; d++) s += p2[d] * Wg[d * NGRP + t];
        out[b * NGRP + t] = s;
    } else if (t >= 64 && t < 64 + NGRP * NFAM) {
        int u = t - 64;
        int grp = u / NFAM, f = u - grp * NFAM;
        float s = bf[grp * NFAM + f];
        for (int d = 0; d < F2; d++) s += p2[d] * Wf[(size_t)grp * F2 * NFAM + d * NFAM + f];
        out[NG * NGRP + (size_t)grp * NG * NFAM + b * NFAM + f] = s;
    }
}

// ---------------- launch ----------------
extern "C" void kernel_launch(void* const* d_in, const int* in_sizes, int n_in,
                              void* d_out, int out_size)
{
    const float* x    = (const float*)d_in[0];
    const void*  eidx = d_in[1];
    const void*  batc = d_in[2];
    const float* W1   = (const float*)d_in[3];
    const float* b1   = (const float*)d_in[4];
    const float* W2   = (const float*)d_in[5];
    const float* b2   = (const float*)d_in[6];
    const float* Wg   = (const float*)d_in[7];
    const float* bg   = (const float*)d_in[8];
    const float* Wf   = (const float*)d_in[9];
    const float* bf   = (const float*)d_in[10];
    float* out = (float*)d_out;

    __half *xw1h, *r1h, *h2h;
    cudaGetSymbolAddress((void**)&xw1h, g_xw1h);
    cudaGetSymbolAddress((void**)&r1h,  g_r1h);
    cudaGetSymbolAddress((void**)&h2h,  g_h2h);

    cudaFuncSetAttribute(k_hgemm, cudaFuncAttributeMaxDynamicSharedMemorySize, HSMEM_BYTES);

    // 1: dtype detect   2: init   3: edge convert + degree count (fused)
    k_detect<<<1, 1>>>((const unsigned int*)eidx);
    k_init<<<(INIT_N + 255) / 256, 256>>>();
    k_conv_edges<<<(NE + 255) / 256, 256>>>((const int*)eidx);

    // 4 (profiled slot): GEMM1 tensor cores
    k_hgemm<<<(NN + 127) / 128, 256, HSMEM_BYTES>>>(x, W1, xw1h, NN);

    // batch convert + CSR build
    k_conv_batch<<<(NN + 255) / 256, 256>>>((const int*)batc);
    k_scan_local<<<NBLK, SB>>>();
    k_scan_bsum<<<1, 256>>>();
    k_scan_add<<<NBLK, SB>>>();      // also computes dinv
    k_fill<<<(NE + 255) / 256, 256>>>();

    // layer 1 aggregate + relu (fp16 out), layer 2 aggregate (fp16 out)
    k_gather<true><<<(NN * 32 + 255) / 256, 256>>>(xw1h, b1, r1h);
    k_gather<false><<<(NN * 32 + 255) / 256, 256>>>(r1h, nullptr, h2h);

    // pool (+counts) then fused W2 + heads
    k_pool<<<(NN + 63) / 64, 128>>>();
    k_w2head<<<NG, 256>>>(W2, b2, Wg, bg, Wf, bf, out);
}

// round 10
// speedup vs baseline: 9.4390x; 1.0524x over previous
#include <cuda_runtime.h>
#include <cuda_bf16.h>
#include <cuda_fp16.h>
#include <math.h>

// ---------------- problem constants ----------------
#define NN 100000          // nodes
#define NE 1600000         // edges
#define NG 512             // graphs
#define F1 128             // IN_F == H1
#define F2 256             // H2
#define NGRP 16
#define NFAM 10

#define SB 512
#define NBLK ((NN + SB - 1) / SB)   // 196 scan blocks
#define INIT_N (NG * F2)

// HMMA GEMM1 geometry
#define ASTRIDE 136                     // 128 + 8 halves pad
#define HSMEM_BYTES (2 * 128 * ASTRIDE * 2)   // A + B panels, fp16

// ---------------- device scratch (no allocations allowed) ----------------
__device__ __half g_xw1h[ (size_t)NN * F1 ];  // x @ W1          (fp16)
__device__ __half g_r1h [ (size_t)NN * F1 ];  // relu(A*xw1+b1)  (fp16)
__device__ __half g_h2h [ (size_t)NN * F1 ];  // A_hat * r1      (fp16)
__device__ float  g_psum[ NG * F1 ];
__device__ float  g_dinv[ NN ];
__device__ float  g_cnts[ NG ];
__device__ int2   g_e2  [ NE ];               // (src, dst) interleaved
__device__ int    g_batch[ NN ];
__device__ int    g_is64;
__device__ int    g_degi  [ NN ];
__device__ int    g_off   [ NN ];
__device__ int    g_cursor[ NN ];
__device__ int    g_bsum  [ 256 ];
__device__ int2   g_csr   [ NE ];             // (src, coef bits) interleaved

// ---------------- dtype detection (one warp, parallel loads) ----------------
__global__ void k_detect(const unsigned int* __restrict__ e) {
    unsigned int v = e[2 * threadIdx.x + 1];
    unsigned int m = __ballot_sync(0xffffffffu, v != 0u);
    if (threadIdx.x == 0) g_is64 = (m == 0u) ? 1 : 0;
}

// ---------------- init ----------------
__global__ void k_init() {
    int i = blockIdx.x * blockDim.x + threadIdx.x;
    if (i < NN) g_degi[i] = 0;
    if (i < NG * F1) g_psum[i] = 0.0f;
    if (i < NG) g_cnts[i] = 0.0f;
}

// ---------------- edge convert + degree count (fused, one pass) ----------------
__global__ void k_conv_edges(const int* __restrict__ in) {
    int e = blockIdx.x * blockDim.x + threadIdx.x;
    if (e >= NE) return;
    int s, d;
    if (g_is64) { s = in[2 * e]; d = in[2 * (NE + e)]; }
    else        { s = in[e];     d = in[NE + e]; }
    g_e2[e] = make_int2(s, d);
    atomicAdd(&g_degi[d], 1);
}

__global__ void k_conv_batch(const int* __restrict__ in) {
    int i = blockIdx.x * blockDim.x + threadIdx.x;
    if (i >= NN) return;
    g_batch[i] = g_is64 ? in[2 * i] : in[i];
}

// ---------------- exclusive scan over g_degi -> g_off (+ dinv fold) ------------
__global__ void k_scan_local() {
    __shared__ int sh[SB];
    int i = blockIdx.x * SB + threadIdx.x;
    int v = (i < NN) ? g_degi[i] : 0;
    sh[threadIdx.x] = v;
    __syncthreads();
    for (int off = 1; off < SB; off <<= 1) {
        int t = (threadIdx.x >= off) ? sh[threadIdx.x - off] : 0;
        __syncthreads();
        sh[threadIdx.x] += t;
        __syncthreads();
    }
    if (i < NN) g_off[i] = sh[threadIdx.x] - v;
    if (threadIdx.x == SB - 1) g_bsum[blockIdx.x] = sh[SB - 1];
}

__global__ void k_scan_bsum() {
    __shared__ int sh[256];
    int t = threadIdx.x;
    int v = (t < NBLK) ? g_bsum[t] : 0;
    sh[t] = v;
    __syncthreads();
    for (int off = 1; off < 256; off <<= 1) {
        int u = (t >= off) ? sh[t - off] : 0;
        __syncthreads();
        sh[t] += u;
        __syncthreads();
    }
    if (t < NBLK) g_bsum[t] = sh[t] - v;
}

__global__ void k_scan_add() {
    int i = blockIdx.x * SB + threadIdx.x;
    if (i < NN) {
        int o = g_off[i] + g_bsum[blockIdx.x];
        g_off[i] = o;
        g_cursor[i] = o;
        g_dinv[i] = rsqrtf((float)(g_degi[i] + 1));
    }
}

// ---------------- CSR fill: per-dst segments of (src, coef) ----------------
__global__ void k_fill() {
    int e = blockIdx.x * blockDim.x + threadIdx.x;
    if (e >= NE) return;
    int2 sd = g_e2[e];
    float coef = g_dinv[sd.x] * g_dinv[sd.y];
    int slot = atomicAdd(&g_cursor[sd.y], 1);
    g_csr[slot] = make_int2(sd.x, __float_as_int(coef));
}

// ---------------- HMMA GEMM1: C[M,128] = A[M,128] * B[128,128], fp16 out --------
__launch_bounds__(256)
__global__ void k_hgemm(const float* __restrict__ A, const float* __restrict__ B,
                        __half* __restrict__ C, int M)
{
    extern __shared__ __half smem[];
    __half* As  = smem;                 // [128][ASTRIDE]
    __half* Bsm = smem + 128 * ASTRIDE; // [128][ASTRIDE]

    const int tid  = threadIdx.x;
    const int lane = tid & 31;
    const int wid  = tid >> 5;
    const int wm   = wid >> 1;
    const int wn   = wid & 1;
    const int row0 = blockIdx.x * 128;

#pragma unroll
    for (int i = 0; i < 16; i++) {
        int idx = tid + i * 256;
        int row = idx >> 5;
        int c4  = idx & 31;
        float4 v = make_float4(0.f, 0.f, 0.f, 0.f);
        if (row0 + row < M)
            v = *(const float4*)(A + (size_t)(row0 + row) * 128 + c4 * 4);
        __half2 h01 = __floats2half2_rn(v.x, v.y);
        __half2 h23 = __floats2half2_rn(v.z, v.w);
        uint2 pk;
        pk.x = *(unsigned int*)&h01;
        pk.y = *(unsigned int*)&h23;
        *(uint2*)(As + row * ASTRIDE + c4 * 4) = pk;

        float4 w = *(const float4*)(B + (size_t)row * 128 + c4 * 4);
        __half2 w01 = __floats2half2_rn(w.x, w.y);
        __half2 w23 = __floats2half2_rn(w.z, w.w);
        uint2 pw;
        pw.x = *(unsigned int*)&w01;
        pw.y = *(unsigned int*)&w23;
        *(uint2*)(Bsm + row * ASTRIDE + c4 * 4) = pw;
    }
    __syncthreads();

    float acc[2][8][4];
#pragma unroll
    for (int mt = 0; mt < 2; mt++)
#pragma unroll
        for (int nt = 0; nt < 8; nt++)
#pragma unroll
            for (int r = 0; r < 4; r++) acc[mt][nt][r] = 0.0f;

#pragma unroll
    for (int kc = 0; kc < 8; kc++) {
        int k0 = kc * 16;
        unsigned int a[2][4];
#pragma unroll
        for (int mt = 0; mt < 2; mt++) {
            int r = wm * 32 + mt * 16 + (lane & 15);
            int c = k0 + (lane >> 4) * 8;
            unsigned int addr = (unsigned int)__cvta_generic_to_shared(As + r * ASTRIDE + c);
            asm volatile("ldmatrix.sync.aligned.m8n8.x4.shared.b16 {%0,%1,%2,%3}, [%4];"
                         : "=r"(a[mt][0]), "=r"(a[mt][1]), "=r"(a[mt][2]), "=r"(a[mt][3])
                         : "r"(addr));
        }
        unsigned int b[8][2];
#pragma unroll
        for (int p = 0; p < 4; p++) {
            int r = k0 + (lane & 15);
            int c = wn * 64 + p * 16 + (lane >> 4) * 8;
            unsigned int addr = (unsigned int)__cvta_generic_to_shared(Bsm + r * ASTRIDE + c);
            unsigned int r0, r1, r2, r3;
            asm volatile("ldmatrix.sync.aligned.m8n8.x4.trans.shared.b16 {%0,%1,%2,%3}, [%4];"
                         : "=r"(r0), "=r"(r1), "=r"(r2), "=r"(r3)
                         : "r"(addr));
            b[p * 2][0] = r0; b[p * 2][1] = r1;
            b[p * 2 + 1][0] = r2; b[p * 2 + 1][1] = r3;
        }
#pragma unroll
        for (int mt = 0; mt < 2; mt++)
#pragma unroll
            for (int nt = 0; nt < 8; nt++)
                asm volatile("mma.sync.aligned.m16n8k16.row.col.f32.f16.f16.f32 "
                             "{%0,%1,%2,%3}, {%4,%5,%6,%7}, {%8,%9}, {%0,%1,%2,%3};"
                             : "+f"(acc[mt][nt][0]), "+f"(acc[mt][nt][1]),
                               "+f"(acc[mt][nt][2]), "+f"(acc[mt][nt][3])
                             : "r"(a[mt][0]), "r"(a[mt][1]), "r"(a[mt][2]), "r"(a[mt][3]),
                               "r"(b[nt][0]), "r"(b[nt][1]));
    }

    const int g  = lane >> 2;
    const int t4 = lane & 3;
#pragma unroll
    for (int mt = 0; mt < 2; mt++) {
#pragma unroll
        for (int nt = 0; nt < 8; nt++) {
            int row = row0 + wm * 32 + mt * 16 + g;
            int col = wn * 64 + nt * 8 + t4 * 2;
            if (row < M) {
                __half2 h = __floats2half2_rn(acc[mt][nt][0], acc[mt][nt][1]);
                *(__half2*)(C + (size_t)row * 128 + col) = h;
            }
            if (row + 8 < M) {
                __half2 h = __floats2half2_rn(acc[mt][nt][2], acc[mt][nt][3]);
                *(__half2*)(C + (size_t)(row + 8) * 128 + col) = h;
            }
        }
    }
}

// ---------------- CSR gather over F=128 (fp16 in/out), self-loop folded ---------
template<bool RELU_OUT>
__launch_bounds__(256)
__global__ void k_gather(const __half* __restrict__ in, const float* __restrict__ bias,
                         __half* __restrict__ outh)
{
    int d = (blockIdx.x * 256 + threadIdx.x) >> 5;
    if (d >= NN) return;
    int lane = threadIdx.x & 31;
    int beg = g_off[d];
    int end = beg + g_degi[d];

    float4 acc = make_float4(0.f, 0.f, 0.f, 0.f);

#define LOAD4(sidx, f01, f23)                                               \
    {                                                                       \
        uint2 u = *(const uint2*)(in + (size_t)(sidx) * 128 + lane * 4);    \
        f01 = __half22float2(*(__half2*)&u.x);                              \
        f23 = __half22float2(*(__half2*)&u.y);                              \
    }

    int j = beg;
    for (; j + 3 < end; j += 4) {
        int2 e0 = g_csr[j],     e1 = g_csr[j + 1];
        int2 e2 = g_csr[j + 2], e3 = g_csr[j + 3];
        float c0 = __int_as_float(e0.y), c1 = __int_as_float(e1.y);
        float c2 = __int_as_float(e2.y), c3 = __int_as_float(e3.y);
        float2 a01, a23, b01, b23, e01, e23, f01, f23;
        LOAD4(e0.x, a01, a23); LOAD4(e1.x, b01, b23);
        LOAD4(e2.x, e01, e23); LOAD4(e3.x, f01, f23);
        acc.x += c0 * a01.x + c1 * b01.x + c2 * e01.x + c3 * f01.x;
        acc.y += c0 * a01.y + c1 * b01.y + c2 * e01.y + c3 * f01.y;
        acc.z += c0 * a23.x + c1 * b23.x + c2 * e23.x + c3 * f23.x;
        acc.w += c0 * a23.y + c1 * b23.y + c2 * e23.y + c3 * f23.y;
    }
    for (; j < end; j++) {
        int2 e0 = g_csr[j];
        float c0 = __int_as_float(e0.y);
        float2 a01, a23;
        LOAD4(e0.x, a01, a23);
        acc.x += c0 * a01.x; acc.y += c0 * a01.y;
        acc.z += c0 * a23.x; acc.w += c0 * a23.y;
    }

    // self loop
    {
        float dv = g_dinv[d];
        float c = dv * dv;
        float2 a01, a23;
        LOAD4(d, a01, a23);
        acc.x += c * a01.x; acc.y += c * a01.y;
        acc.z += c * a23.x; acc.w += c * a23.y;
    }
#undef LOAD4

    if (RELU_OUT) {
        float4 bb = *(const float4*)(bias + lane * 4);
        acc.x = fmaxf(acc.x + bb.x, 0.f);
        acc.y = fmaxf(acc.y + bb.y, 0.f);
        acc.z = fmaxf(acc.z + bb.z, 0.f);
        acc.w = fmaxf(acc.w + bb.w, 0.f);
    }
    __half2 h0 = __floats2half2_rn(acc.x, acc.y);
    __half2 h1 = __floats2half2_rn(acc.z, acc.w);
    uint2 pk;
    pk.x = *(unsigned int*)&h0;
    pk.y = *(unsigned int*)&h1;
    *(uint2*)(outh + (size_t)d * 128 + lane * 4) = pk;
}

// ---------------- pooling over h2 fp16 (batch sorted) + counts ----------------
__global__ void k_pool()
{
    int f  = threadIdx.x;                 // 128 = F1
    int n0 = blockIdx.x * 64;
    int n1 = min(n0 + 64, NN);
    if (n0 >= NN) return;
    int curg = g_batch[n0];
    float acc = 0.0f;
    int   cnt = 0;
    for (int n = n0; n < n1; n++) {
        int gg = g_batch[n];
        if (gg != curg) {
            atomicAdd(&g_psum[curg * F1 + f], acc);
            if (f == 0) atomicAdd(&g_cnts[curg], (float)cnt);
            acc = 0.0f; cnt = 0; curg = gg;
        }
        acc += __half2float(g_h2h[(size_t)n * F1 + f]);
        cnt++;
    }
    atomicAdd(&g_psum[curg * F1 + f], acc);
    if (f == 0) atomicAdd(&g_cnts[curg], (float)cnt);
}

// ---------------- fused: pooled@W2+b2 then heads ----------------
__global__ void k_w2head(const float* __restrict__ W2, const float* __restrict__ b2,
                         const float* __restrict__ Wg, const float* __restrict__ bg,
                         const float* __restrict__ Wf, const float* __restrict__ bf,
                         float* __restrict__ out)
{
    __shared__ float p[F1];
    __shared__ float p2[F2];
    int b = blockIdx.x, t = threadIdx.x;          // 256 threads
    float inv = 1.0f / fmaxf(g_cnts[b], 1.0f);
    if (t < F1) p[t] = g_psum[b * F1 + t] * inv;
    __syncthreads();
    float a = b2[t];
#pragma unroll 4
    for (int d = 0; d < F1; d++) a += p[d] * W2[d * F2 + t];
    p2[t] = a;
    __syncthreads();
    if (t < NGRP) {
        float s = bg[t];
        for (int d = 0; d < F2; d++) s += p2[d] * Wg[d * NGRP + t];
        out[b * NGRP + t] = s;
    } else if (t >= 64 && t < 64 + NGRP * NFAM) {
        int u = t - 64;
        int grp = u / NFAM, f = u - grp * NFAM;
        float s = bf[grp * NFAM + f];
        for (int d = 0; d < F2; d++) s += p2[d] * Wf[(size_t)grp * F2 * NFAM + d * NFAM + f];
        out[NG * NGRP + (size_t)grp * NG * NFAM + b * NFAM + f] = s;
    }
}

// ---------------- launch ----------------
extern "C" void kernel_launch(void* const* d_in, const int* in_sizes, int n_in,
                              void* d_out, int out_size)
{
    const float* x    = (const float*)d_in[0];
    const void*  eidx = d_in[1];
    const void*  batc = d_in[2];
    const float* W1   = (const float*)d_in[3];
    const float* b1   = (const float*)d_in[4];
    const float* W2   = (const float*)d_in[5];
    const float* b2   = (const float*)d_in[6];
    const float* Wg   = (const float*)d_in[7];
    const float* bg   = (const float*)d_in[8];
    const float* Wf   = (const float*)d_in[9];
    const float* bf   = (const float*)d_in[10];
    float* out = (float*)d_out;

    __half *xw1h, *r1h, *h2h;
    cudaGetSymbolAddress((void**)&xw1h, g_xw1h);
    cudaGetSymbolAddress((void**)&r1h,  g_r1h);
    cudaGetSymbolAddress((void**)&h2h,  g_h2h);

    cudaFuncSetAttribute(k_hgemm, cudaFuncAttributeMaxDynamicSharedMemorySize, HSMEM_BYTES);

    // side stream + events for fork-join (created once, outside capture:
    // the first — uncaptured — correctness call initializes them; every call
    // performs the identical launch sequence, so the work is deterministic).
    static cudaStream_t sB = nullptr;
    static cudaEvent_t evFork = nullptr, evDet = nullptr, evJoin = nullptr;
    if (sB == nullptr) {
        cudaStreamCreateWithFlags(&sB, cudaStreamNonBlocking);
        cudaEventCreateWithFlags(&evFork, cudaEventDisableTiming);
        cudaEventCreateWithFlags(&evDet,  cudaEventDisableTiming);
        cudaEventCreateWithFlags(&evJoin, cudaEventDisableTiming);
    }

    // ---- fork: side stream runs GEMM1 (independent of graph build) ----
    cudaEventRecord(evFork, 0);
    cudaStreamWaitEvent(sB, evFork, 0);
    k_hgemm<<<(NN + 127) / 128, 256, HSMEM_BYTES, sB>>>(x, W1, xw1h, NN);

    // ---- main stream: dtype detect + CSR build chain ----
    k_detect<<<1, 32>>>((const unsigned int*)eidx);
    cudaEventRecord(evDet, 0);
    k_init<<<(INIT_N + 255) / 256, 256>>>();
    k_conv_edges<<<(NE + 255) / 256, 256>>>((const int*)eidx);
    k_scan_local<<<NBLK, SB>>>();
    k_scan_bsum<<<1, 256>>>();
    k_scan_add<<<NBLK, SB>>>();      // also computes dinv
    k_fill<<<(NE + 255) / 256, 256>>>();

    // side stream: batch convert (needs detect result)
    cudaStreamWaitEvent(sB, evDet, 0);
    k_conv_batch<<<(NN + 255) / 256, 256, 0, sB>>>((const int*)batc);
    cudaEventRecord(evJoin, sB);

    // ---- join: gathers need xw1h (sB) + CSR (main) ----
    cudaStreamWaitEvent(0, evJoin, 0);

    k_gather<true><<<(NN * 32 + 255) / 256, 256>>>(xw1h, b1, r1h);
    k_gather<false><<<(NN * 32 + 255) / 256, 256>>>(r1h, nullptr, h2h);

    // pool (+counts) then fused W2 + heads
    k_pool<<<(NN + 63) / 64, 128>>>();
    k_w2head<<<NG, 256>>>(W2, b2, Wg, bg, Wf, bf, out);
}

// round 11
// speedup vs baseline: 9.8248x; 1.0409x over previous
#include <cuda_runtime.h>
#include <cuda_bf16.h>
#include <cuda_fp16.h>
#include <math.h>

// ---------------- problem constants ----------------
#define NN 100000          // nodes
#define NE 1600000         // edges
#define NG 512             // graphs
#define F1 128             // IN_F == H1
#define F2 256             // H2
#define NGRP 16
#define NFAM 10

#define SB 512
#define NBLK ((NN + SB - 1) / SB)   // 196 scan blocks
#define INIT_N (NG * F2)

// HMMA GEMM1 geometry
#define ASTRIDE 136                     // 128 + 8 halves pad
#define HSMEM_BYTES (2 * 128 * ASTRIDE * 2)   // A + B panels, fp16

// ---------------- device scratch (no allocations allowed) ----------------
__device__ __half g_xw1h[ (size_t)NN * F1 ];  // x @ W1          (fp16)
__device__ __half g_r1h [ (size_t)NN * F1 ];  // relu(A*xw1+b1)  (fp16)
__device__ float  g_psum[ NG * F1 ];
__device__ float  g_dinv[ NN ];
__device__ float  g_cnts[ NG ];
__device__ int    g_batch[ NN ];
__device__ int    g_is64;
__device__ int    g_degi  [ NN ];
__device__ int    g_off   [ NN ];
__device__ int    g_cursor[ NN ];
__device__ int    g_bsum  [ 256 ];
__device__ int2   g_csr   [ NE ];             // (src, coef bits) interleaved

// ---------------- dtype detection (one warp, parallel loads) ----------------
__global__ void k_detect(const unsigned int* __restrict__ e) {
    unsigned int v = e[2 * threadIdx.x + 1];
    unsigned int m = __ballot_sync(0xffffffffu, v != 0u);
    if (threadIdx.x == 0) g_is64 = (m == 0u) ? 1 : 0;
}

// ---------------- init ----------------
__global__ void k_init() {
    int i = blockIdx.x * blockDim.x + threadIdx.x;
    if (i < NN) g_degi[i] = 0;
    if (i < NG * F1) g_psum[i] = 0.0f;
    if (i < NG) g_cnts[i] = 0.0f;
}

// ---------------- degree count (dst only, 2 edges/thread, vectorized) ----------
__global__ void k_deg(const int* __restrict__ in) {
    int t = blockIdx.x * blockDim.x + threadIdx.x;
    int e2 = t * 2;
    if (e2 >= NE) return;
    int d0, d1;
    if (g_is64) {
        // dst at int offsets 2*(NE+e): pairs are 16B-aligned since NE, e2 even
        int4 v = *(const int4*)(in + 2 * (NE + e2));
        d0 = v.x; d1 = v.z;
    } else {
        int2 v = *(const int2*)(in + NE + e2);
        d0 = v.x; d1 = v.y;
    }
    atomicAdd(&g_degi[d0], 1);
    atomicAdd(&g_degi[d1], 1);
}

__global__ void k_conv_batch(const int* __restrict__ in) {
    int i = blockIdx.x * blockDim.x + threadIdx.x;
    if (i >= NN) return;
    g_batch[i] = g_is64 ? in[2 * i] : in[i];
}

// ---------------- exclusive scan over g_degi -> g_off (+ dinv fold) ------------
__global__ void k_scan_local() {
    __shared__ int sh[SB];
    int i = blockIdx.x * SB + threadIdx.x;
    int v = (i < NN) ? g_degi[i] : 0;
    sh[threadIdx.x] = v;
    __syncthreads();
    for (int off = 1; off < SB; off <<= 1) {
        int t = (threadIdx.x >= off) ? sh[threadIdx.x - off] : 0;
        __syncthreads();
        sh[threadIdx.x] += t;
        __syncthreads();
    }
    if (i < NN) g_off[i] = sh[threadIdx.x] - v;
    if (threadIdx.x == SB - 1) g_bsum[blockIdx.x] = sh[SB - 1];
}

__global__ void k_scan_bsum() {
    __shared__ int sh[256];
    int t = threadIdx.x;
    int v = (t < NBLK) ? g_bsum[t] : 0;
    sh[t] = v;
    __syncthreads();
    for (int off = 1; off < 256; off <<= 1) {
        int u = (t >= off) ? sh[t - off] : 0;
        __syncthreads();
        sh[t] += u;
        __syncthreads();
    }
    if (t < NBLK) g_bsum[t] = sh[t] - v;
}

__global__ void k_scan_add() {
    int i = blockIdx.x * SB + threadIdx.x;
    if (i < NN) {
        int o = g_off[i] + g_bsum[blockIdx.x];
        g_off[i] = o;
        g_cursor[i] = o;
        g_dinv[i] = rsqrtf((float)(g_degi[i] + 1));
    }
}

// ---------------- CSR fill: reads raw edge list directly ----------------
__global__ void k_fill(const int* __restrict__ in) {
    int e = blockIdx.x * blockDim.x + threadIdx.x;
    if (e >= NE) return;
    int s, d;
    if (g_is64) { s = in[2 * e]; d = in[2 * (NE + e)]; }
    else        { s = in[e];     d = in[NE + e]; }
    float coef = g_dinv[s] * g_dinv[d];
    int slot = atomicAdd(&g_cursor[d], 1);
    g_csr[slot] = make_int2(s, __float_as_int(coef));
}

// ---------------- HMMA GEMM1: C[M,128] = A[M,128] * B[128,128], fp16 out --------
__launch_bounds__(256)
__global__ void k_hgemm(const float* __restrict__ A, const float* __restrict__ B,
                        __half* __restrict__ C, int M)
{
    extern __shared__ __half smem[];
    __half* As  = smem;                 // [128][ASTRIDE]
    __half* Bsm = smem + 128 * ASTRIDE; // [128][ASTRIDE]

    const int tid  = threadIdx.x;
    const int lane = tid & 31;
    const int wid  = tid >> 5;
    const int wm   = wid >> 1;
    const int wn   = wid & 1;
    const int row0 = blockIdx.x * 128;

#pragma unroll
    for (int i = 0; i < 16; i++) {
        int idx = tid + i * 256;
        int row = idx >> 5;
        int c4  = idx & 31;
        float4 v = make_float4(0.f, 0.f, 0.f, 0.f);
        if (row0 + row < M)
            v = *(const float4*)(A + (size_t)(row0 + row) * 128 + c4 * 4);
        __half2 h01 = __floats2half2_rn(v.x, v.y);
        __half2 h23 = __floats2half2_rn(v.z, v.w);
        uint2 pk;
        pk.x = *(unsigned int*)&h01;
        pk.y = *(unsigned int*)&h23;
        *(uint2*)(As + row * ASTRIDE + c4 * 4) = pk;

        float4 w = *(const float4*)(B + (size_t)row * 128 + c4 * 4);
        __half2 w01 = __floats2half2_rn(w.x, w.y);
        __half2 w23 = __floats2half2_rn(w.z, w.w);
        uint2 pw;
        pw.x = *(unsigned int*)&w01;
        pw.y = *(unsigned int*)&w23;
        *(uint2*)(Bsm + row * ASTRIDE + c4 * 4) = pw;
    }
    __syncthreads();

    float acc[2][8][4];
#pragma unroll
    for (int mt = 0; mt < 2; mt++)
#pragma unroll
        for (int nt = 0; nt < 8; nt++)
#pragma unroll
            for (int r = 0; r < 4; r++) acc[mt][nt][r] = 0.0f;

#pragma unroll
    for (int kc = 0; kc < 8; kc++) {
        int k0 = kc * 16;
        unsigned int a[2][4];
#pragma unroll
        for (int mt = 0; mt < 2; mt++) {
            int r = wm * 32 + mt * 16 + (lane & 15);
            int c = k0 + (lane >> 4) * 8;
            unsigned int addr = (unsigned int)__cvta_generic_to_shared(As + r * ASTRIDE + c);
            asm volatile("ldmatrix.sync.aligned.m8n8.x4.shared.b16 {%0,%1,%2,%3}, [%4];"
                         : "=r"(a[mt][0]), "=r"(a[mt][1]), "=r"(a[mt][2]), "=r"(a[mt][3])
                         : "r"(addr));
        }
        unsigned int b[8][2];
#pragma unroll
        for (int p = 0; p < 4; p++) {
            int r = k0 + (lane & 15);
            int c = wn * 64 + p * 16 + (lane >> 4) * 8;
            unsigned int addr = (unsigned int)__cvta_generic_to_shared(Bsm + r * ASTRIDE + c);
            unsigned int r0, r1, r2, r3;
            asm volatile("ldmatrix.sync.aligned.m8n8.x4.trans.shared.b16 {%0,%1,%2,%3}, [%4];"
                         : "=r"(r0), "=r"(r1), "=r"(r2), "=r"(r3)
                         : "r"(addr));
            b[p * 2][0] = r0; b[p * 2][1] = r1;
            b[p * 2 + 1][0] = r2; b[p * 2 + 1][1] = r3;
        }
#pragma unroll
        for (int mt = 0; mt < 2; mt++)
#pragma unroll
            for (int nt = 0; nt < 8; nt++)
                asm volatile("mma.sync.aligned.m16n8k16.row.col.f32.f16.f16.f32 "
                             "{%0,%1,%2,%3}, {%4,%5,%6,%7}, {%8,%9}, {%0,%1,%2,%3};"
                             : "+f"(acc[mt][nt][0]), "+f"(acc[mt][nt][1]),
                               "+f"(acc[mt][nt][2]), "+f"(acc[mt][nt][3])
                             : "r"(a[mt][0]), "r"(a[mt][1]), "r"(a[mt][2]), "r"(a[mt][3]),
                               "r"(b[nt][0]), "r"(b[nt][1]));
    }

    const int g  = lane >> 2;
    const int t4 = lane & 3;
#pragma unroll
    for (int mt = 0; mt < 2; mt++) {
#pragma unroll
        for (int nt = 0; nt < 8; nt++) {
            int row = row0 + wm * 32 + mt * 16 + g;
            int col = wn * 64 + nt * 8 + t4 * 2;
            if (row < M) {
                __half2 h = __floats2half2_rn(acc[mt][nt][0], acc[mt][nt][1]);
                *(__half2*)(C + (size_t)row * 128 + col) = h;
            }
            if (row + 8 < M) {
                __half2 h = __floats2half2_rn(acc[mt][nt][2], acc[mt][nt][3]);
                *(__half2*)(C + (size_t)(row + 8) * 128 + col) = h;
            }
        }
    }
}

// ---------------- layer-1 gather (warp per node): r1 = relu(A_hat*xw1 + b1) -----
__launch_bounds__(256)
__global__ void k_gather1(const __half* __restrict__ in, const float* __restrict__ bias,
                          __half* __restrict__ outh)
{
    int d = (blockIdx.x * 256 + threadIdx.x) >> 5;
    if (d >= NN) return;
    int lane = threadIdx.x & 31;
    int beg = g_off[d];
    int end = beg + g_degi[d];

    float4 acc = make_float4(0.f, 0.f, 0.f, 0.f);

#define LOAD4(sidx, f01, f23)                                               \
    {                                                                       \
        uint2 u = *(const uint2*)(in + (size_t)(sidx) * 128 + lane * 4);    \
        f01 = __half22float2(*(__half2*)&u.x);                              \
        f23 = __half22float2(*(__half2*)&u.y);                              \
    }

    int j = beg;
    for (; j + 3 < end; j += 4) {
        int2 e0 = g_csr[j],     e1 = g_csr[j + 1];
        int2 e2 = g_csr[j + 2], e3 = g_csr[j + 3];
        float c0 = __int_as_float(e0.y), c1 = __int_as_float(e1.y);
        float c2 = __int_as_float(e2.y), c3 = __int_as_float(e3.y);
        float2 a01, a23, b01, b23, e01, e23, f01, f23;
        LOAD4(e0.x, a01, a23); LOAD4(e1.x, b01, b23);
        LOAD4(e2.x, e01, e23); LOAD4(e3.x, f01, f23);
        acc.x += c0 * a01.x + c1 * b01.x + c2 * e01.x + c3 * f01.x;
        acc.y += c0 * a01.y + c1 * b01.y + c2 * e01.y + c3 * f01.y;
        acc.z += c0 * a23.x + c1 * b23.x + c2 * e23.x + c3 * f23.x;
        acc.w += c0 * a23.y + c1 * b23.y + c2 * e23.y + c3 * f23.y;
    }
    for (; j < end; j++) {
        int2 e0 = g_csr[j];
        float c0 = __int_as_float(e0.y);
        float2 a01, a23;
        LOAD4(e0.x, a01, a23);
        acc.x += c0 * a01.x; acc.y += c0 * a01.y;
        acc.z += c0 * a23.x; acc.w += c0 * a23.y;
    }

    // self loop
    {
        float dv = g_dinv[d];
        float c = dv * dv;
        float2 a01, a23;
        LOAD4(d, a01, a23);
        acc.x += c * a01.x; acc.y += c * a01.y;
        acc.z += c * a23.x; acc.w += c * a23.y;
    }

    float4 bb = *(const float4*)(bias + lane * 4);
    acc.x = fmaxf(acc.x + bb.x, 0.f);
    acc.y = fmaxf(acc.y + bb.y, 0.f);
    acc.z = fmaxf(acc.z + bb.z, 0.f);
    acc.w = fmaxf(acc.w + bb.w, 0.f);

    __half2 h0 = __floats2half2_rn(acc.x, acc.y);
    __half2 h1 = __floats2half2_rn(acc.z, acc.w);
    uint2 pk;
    pk.x = *(unsigned int*)&h0;
    pk.y = *(unsigned int*)&h1;
    *(uint2*)(outh + (size_t)d * 128 + lane * 4) = pk;
#undef LOAD4
}

// ---------------- fused layer-2 gather + pool ----------------
// psum[g] += sum_{d in g} ( sum_e coef_e*r1[src_e] + dinv[d]^2*r1[d] ),
// register-accumulated across the warp's 8 consecutive nodes (batch sorted),
// flushed via atomics only on graph change. Also counts nodes per graph.
__launch_bounds__(256)
__global__ void k_gpool(const __half* __restrict__ r1)
{
    int warp = threadIdx.x >> 5;
    int lane = threadIdx.x & 31;
    int n0 = blockIdx.x * 64 + warp * 8;
    if (n0 >= NN) return;
    int n1 = min(n0 + 8, NN);

    int curg = g_batch[n0];
    float4 acc = make_float4(0.f, 0.f, 0.f, 0.f);
    int cnt = 0;

#define LOAD4(sidx, f01, f23)                                               \
    {                                                                       \
        uint2 u = *(const uint2*)(r1 + (size_t)(sidx) * 128 + lane * 4);    \
        f01 = __half22float2(*(__half2*)&u.x);                              \
        f23 = __half22float2(*(__half2*)&u.y);                              \
    }

    for (int n = n0; n < n1; n++) {
        int gg = g_batch[n];
        if (gg != curg) {
            float* ps = g_psum + curg * F1 + lane * 4;
            atomicAdd(ps + 0, acc.x); atomicAdd(ps + 1, acc.y);
            atomicAdd(ps + 2, acc.z); atomicAdd(ps + 3, acc.w);
            if (lane == 0) atomicAdd(&g_cnts[curg], (float)cnt);
            acc = make_float4(0.f, 0.f, 0.f, 0.f);
            cnt = 0; curg = gg;
        }

        int beg = g_off[n];
        int end = beg + g_degi[n];
        int j = beg;
        for (; j + 3 < end; j += 4) {
            int2 e0 = g_csr[j],     e1 = g_csr[j + 1];
            int2 e2 = g_csr[j + 2], e3 = g_csr[j + 3];
            float c0 = __int_as_float(e0.y), c1 = __int_as_float(e1.y);
            float c2 = __int_as_float(e2.y), c3 = __int_as_float(e3.y);
            float2 a01, a23, b01, b23, e01, e23, f01, f23;
            LOAD4(e0.x, a01, a23); LOAD4(e1.x, b01, b23);
            LOAD4(e2.x, e01, e23); LOAD4(e3.x, f01, f23);
            acc.x += c0 * a01.x + c1 * b01.x + c2 * e01.x + c3 * f01.x;
            acc.y += c0 * a01.y + c1 * b01.y + c2 * e01.y + c3 * f01.y;
            acc.z += c0 * a23.x + c1 * b23.x + c2 * e23.x + c3 * f23.x;
            acc.w += c0 * a23.y + c1 * b23.y + c2 * e23.y + c3 * f23.y;
        }
        for (; j < end; j++) {
            int2 e0 = g_csr[j];
            float c0 = __int_as_float(e0.y);
            float2 a01, a23;
            LOAD4(e0.x, a01, a23);
            acc.x += c0 * a01.x; acc.y += c0 * a01.y;
            acc.z += c0 * a23.x; acc.w += c0 * a23.y;
        }
        // self loop
        {
            float dv = g_dinv[n];
            float c = dv * dv;
            float2 a01, a23;
            LOAD4(n, a01, a23);
            acc.x += c * a01.x; acc.y += c * a01.y;
            acc.z += c * a23.x; acc.w += c * a23.y;
        }
        cnt++;
    }
#undef LOAD4

    float* ps = g_psum + curg * F1 + lane * 4;
    atomicAdd(ps + 0, acc.x); atomicAdd(ps + 1, acc.y);
    atomicAdd(ps + 2, acc.z); atomicAdd(ps + 3, acc.w);
    if (lane == 0) atomicAdd(&g_cnts[curg], (float)cnt);
}

// ---------------- fused: pooled@W2+b2 then heads ----------------
__global__ void k_w2head(const float* __restrict__ W2, const float* __restrict__ b2,
                         const float* __restrict__ Wg, const float* __restrict__ bg,
                         const float* __restrict__ Wf, const float* __restrict__ bf,
                         float* __restrict__ out)
{
    __shared__ float p[F1];
    __shared__ float p2[F2];
    int b = blockIdx.x, t = threadIdx.x;          // 256 threads
    float cnt = g_cnts[b];
    float inv = 1.0f / fmaxf(cnt, 1.0f);
    if (t < F1) p[t] = g_psum[b * F1 + t] * inv;
    __syncthreads();
    float a = (cnt > 0.f) ? b2[t] : 0.0f;         // empty-graph: pooled stays 0
#pragma unroll 4
    for (int d = 0; d < F1; d++) a += p[d] * W2[d * F2 + t];
    p2[t] = a;
    __syncthreads();
    if (t < NGRP) {
        float s = bg[t];
        for (int d = 0; d < F2; d++) s += p2[d] * Wg[d * NGRP + t];
        out[b * NGRP + t] = s;
    } else if (t >= 64 && t < 64 + NGRP * NFAM) {
        int u = t - 64;
        int grp = u / NFAM, f = u - grp * NFAM;
        float s = bf[grp * NFAM + f];
        for (int d = 0; d < F2; d++) s += p2[d] * Wf[(size_t)grp * F2 * NFAM + d * NFAM + f];
        out[NG * NGRP + (size_t)grp * NG * NFAM + b * NFAM + f] = s;
    }
}

// ---------------- launch ----------------
extern "C" void kernel_launch(void* const* d_in, const int* in_sizes, int n_in,
                              void* d_out, int out_size)
{
    const float* x    = (const float*)d_in[0];
    const void*  eidx = d_in[1];
    const void*  batc = d_in[2];
    const float* W1   = (const float*)d_in[3];
    const float* b1   = (const float*)d_in[4];
    const float* W2   = (const float*)d_in[5];
    const float* b2   = (const float*)d_in[6];
    const float* Wg   = (const float*)d_in[7];
    const float* bg   = (const float*)d_in[8];
    const float* Wf   = (const float*)d_in[9];
    const float* bf   = (const float*)d_in[10];
    float* out = (float*)d_out;

    __half *xw1h, *r1h;
    cudaGetSymbolAddress((void**)&xw1h, g_xw1h);
    cudaGetSymbolAddress((void**)&r1h,  g_r1h);

    cudaFuncSetAttribute(k_hgemm, cudaFuncAttributeMaxDynamicSharedMemorySize, HSMEM_BYTES);

    // side stream + events (created once, outside capture; identical launch
    // sequence every call -> deterministic work).
    static cudaStream_t sB = nullptr;
    static cudaEvent_t evFork = nullptr, evDet = nullptr, evJoin = nullptr;
    if (sB == nullptr) {
        cudaStreamCreateWithFlags(&sB, cudaStreamNonBlocking);
        cudaEventCreateWithFlags(&evFork, cudaEventDisableTiming);
        cudaEventCreateWithFlags(&evDet,  cudaEventDisableTiming);
        cudaEventCreateWithFlags(&evJoin, cudaEventDisableTiming);
    }

    // ---- fork: side stream runs GEMM1 (independent of graph build) ----
    cudaEventRecord(evFork, 0);
    cudaStreamWaitEvent(sB, evFork, 0);
    k_hgemm<<<(NN + 127) / 128, 256, HSMEM_BYTES, sB>>>(x, W1, xw1h, NN);

    // ---- main stream: dtype detect + CSR build chain ----
    k_detect<<<1, 32>>>((const unsigned int*)eidx);
    cudaEventRecord(evDet, 0);
    k_init<<<(INIT_N + 255) / 256, 256>>>();
    k_deg<<<(NE / 2 + 255) / 256, 256>>>((const int*)eidx);
    k_scan_local<<<NBLK, SB>>>();
    k_scan_bsum<<<1, 256>>>();
    k_scan_add<<<NBLK, SB>>>();      // also computes dinv
    k_fill<<<(NE + 255) / 256, 256>>>((const int*)eidx);

    // side stream: batch convert (needs detect result only)
    cudaStreamWaitEvent(sB, evDet, 0);
    k_conv_batch<<<(NN + 255) / 256, 256, 0, sB>>>((const int*)batc);
    cudaEventRecord(evJoin, sB);

    // ---- join: gathers need xw1h + batch (sB) and CSR (main) ----
    cudaStreamWaitEvent(0, evJoin, 0);

    // layer 1 gather (+relu, fp16 out), then fused layer-2 gather+pool
    k_gather1<<<(NN * 32 + 255) / 256, 256>>>(xw1h, b1, r1h);
    k_gpool<<<(NN + 63) / 64, 256>>>(r1h);

    // fused W2 + heads
    k_w2head<<<NG, 256>>>(W2, b2, Wg, bg, Wf, bf, out);
}